// round 4
// baseline (speedup 1.0000x reference)
#include <cuda_runtime.h>
#include <math.h>

// ---------------- dims ----------------
#define NFE 212992              // 8*13*32*64
#define NHE 1064960             // 8*65*32*64
#define NOE 4194304             // 8*256*32*64
#define GSB 208                 // grid-stride blocks for reducing kernels (208*256*4 = NFE)

// ---------------- physics consts ----------------
#define DTs    300.0f
#define KHc    15.0f
#define KVc    0.1f
#define LVc    2.5e6f
#define CPc    1005.0f
#define RGASc  8.314f
#define RDc    287.0f
#define OMEGAc 7.29e-5f
#define EMISc  0.7f
#define SIGMAc 5.67e-8f
#define PIXYc  ((float)(M_PI * 6371000.0 / 33.0))

__constant__ float c_DZ[13]  = {50.f,50.f,50.f,50.f,50.f,75.f,100.f,100.f,100.f,125.f,112.f,75.f,75.f};
__constant__ float c_PRS[13] = {50.f,100.f,150.f,200.f,250.f,300.f,400.f,500.f,600.f,700.f,850.f,925.f,1000.f};

// ---------------- scratch ----------------
__device__ float g_h[NHE], g_o65[NHE];
__device__ float g_o2[NOE];
__device__ float g_fld[5][NFE];                        // z,q,u,v,t post-BN
__device__ float g_zx[NFE], g_zy[NFE], g_zz[NFE], g_ux[NFE], g_vy[NFE];
__device__ float g_w[NFE], g_rate[NFE];
__device__ float g_sua[NFE], g_sva[NFE], g_sta[NFE];   // RK stage fields u,v,t
__device__ float g_ax[NFE], g_ay[NFE], g_az[NFE];      // u-stage derivs
__device__ float g_bx[NFE], g_by[NFE], g_bz[NFE];      // v-stage derivs
__device__ float g_cx[NFE], g_cy[NFE], g_cz[NFE];      // t-stage derivs
__device__ float g_qx[NFE], g_qy[NFE], g_qz[NFE];      // base q derivs
__device__ float g_accu[NFE], g_accv[NFE], g_acct[NFE];
__device__ float g_k4t[NFE], g_dq[NFE], g_dzd[NFE];
__device__ float g_m65[65], g_is65[65], g_m256[256], g_is256[256];
__device__ float g_red[27];
__device__ float g_invpx[32], g_fcor[32];

// red slots: 0..4 field min (z,q,u,v,t); 5..9 field max; 10..14 field sum;
//            15 sarg min; 16 sarg max; 17..21 diff min (z,q,u,v,t); 22..26 diff max

// ---------------- helpers ----------------
__device__ __forceinline__ void atomicMinF(float* a, float v) {
    if (v >= 0.f) atomicMin((int*)a, __float_as_int(v));
    else          atomicMax((unsigned int*)a, __float_as_uint(v));
}
__device__ __forceinline__ void atomicMaxF(float* a, float v) {
    if (v >= 0.f) atomicMax((int*)a, __float_as_int(v));
    else          atomicMin((unsigned int*)a, __float_as_uint(v));
}
__device__ __forceinline__ float avoid_inf1(float t) {
    if (t == 0.f) return 1.f;
    if (fabsf(t) < 1.f) return t > 0.f ? 1.f : -1.f;
    return t;
}

typedef unsigned long long u64;
__device__ __forceinline__ u64 pk2(float lo, float hi) {
    u64 r; asm("mov.b64 %0,{%1,%2};" : "=l"(r) : "f"(lo), "f"(hi)); return r;
}
__device__ __forceinline__ void fm2(u64& d, u64 a, u64 b) {
    asm("fma.rn.f32x2 %0,%1,%2,%0;" : "+l"(d) : "l"(a), "l"(b));
}
__device__ __forceinline__ void upk2(float& lo, float& hi, u64 v) {
    asm("mov.b64 {%0,%1},%2;" : "=f"(lo), "=f"(hi) : "l"(v));
}

struct Pos { int b, v, h, w, i; };
__device__ __forceinline__ Pos decodeP(int i) {
    Pos p; p.i = i; p.w = i & 63; p.h = (i >> 6) & 31;
    int bv = i >> 11; p.v = bv % 13; p.b = bv / 13;
    return p;
}
__device__ __forceinline__ int pidxN(int m, int n) {   // block-replicate pad index
    return m < 2 ? m : (m < n + 2 ? m - 2 : m - 4);
}
__device__ __forceinline__ float dxf(const float* __restrict__ f, const Pos& p) {
    int base = p.i - p.w;
    float g = (f[base + ((p.w + 62) & 63)] - 8.f * f[base + ((p.w + 63) & 63)]
             + 8.f * f[base + ((p.w + 1) & 63)] - f[base + ((p.w + 2) & 63)]) * (1.f / 12.f);
    return g * g_invpx[p.h];
}
__device__ __forceinline__ float dyf(const float* __restrict__ f, const Pos& p) {
    int base = p.i - (p.h << 6);
    float g = (-f[base + (pidxN(p.h, 32) << 6)] + 8.f * f[base + (pidxN(p.h + 1, 32) << 6)]
             - 8.f * f[base + (pidxN(p.h + 3, 32) << 6)] + f[base + (pidxN(p.h + 4, 32) << 6)]) * (1.f / 12.f);
    return g * (1.f / PIXYc);
}
__device__ __forceinline__ float dzf(const float* __restrict__ f, const Pos& p) {
    int base = p.i - (p.v << 11);
    float g = (-f[base + (pidxN(p.v, 13) << 11)] + 8.f * f[base + (pidxN(p.v + 1, 13) << 11)]
             - 8.f * f[base + (pidxN(p.v + 3, 13) << 11)] + f[base + (pidxN(p.v + 4, 13) << 11)]) * (1.f / 12.f);
    return g / c_DZ[p.v];
}

// block reduction (blockDim == 256) -> atomics to g_red; ssum<0 skips sum
__device__ __forceinline__ void blockRed(float vmn, float vmx, float vsum,
                                         int smn, int smx, int ssum) {
    __shared__ float sh[24];
    __syncthreads();
    #pragma unroll
    for (int o = 16; o; o >>= 1) {
        vmn  = fminf(vmn, __shfl_xor_sync(0xffffffffu, vmn, o));
        vmx  = fmaxf(vmx, __shfl_xor_sync(0xffffffffu, vmx, o));
        vsum += __shfl_xor_sync(0xffffffffu, vsum, o);
    }
    int lane = threadIdx.x & 31, wid = threadIdx.x >> 5;
    if (lane == 0) { sh[wid] = vmn; sh[8 + wid] = vmx; sh[16 + wid] = vsum; }
    __syncthreads();
    if (threadIdx.x == 0) {
        float a = sh[0], b = sh[8], s = sh[16];
        #pragma unroll
        for (int k = 1; k < 8; k++) { a = fminf(a, sh[k]); b = fmaxf(b, sh[8 + k]); s += sh[16 + k]; }
        atomicMinF(&g_red[smn], a);
        atomicMaxF(&g_red[smx], b);
        if (ssum >= 0) atomicAdd(&g_red[ssum], s);
    }
}

// ---------------- init ----------------
__global__ void k_init() {
    int t = threadIdx.x;
    if (t < 32) {
        double lat = (90.0 - (double)(t + 1) * (180.0 / 33.0)) * M_PI / 180.0;
        float px = (float)(2.0 * M_PI * 6371000.0 * cos(lat) / 64.0);
        g_invpx[t] = 1.f / px;
        g_fcor[t]  = 2.0f * OMEGAc * sinf((float)lat);
    }
    if (t < 27) {
        float inf = __int_as_float(0x7f800000);
        float v;
        if (t < 5) v = inf;
        else if (t < 10) v = -inf;
        else if (t < 15) v = 0.f;
        else if (t == 15) v = inf;
        else if (t == 16) v = -inf;
        else if (t < 22) v = inf;
        else v = -inf;
        g_red[t] = v;
    }
}

// ---------------- conv3x3 zero-pad (cross-correlation), f32x2 inner ----------------
template <int CI, int CO, int WHICH>
__global__ void __launch_bounds__(256) k_conv(const float* __restrict__ xin,
                                              const float* __restrict__ wt,
                                              const float* __restrict__ bias) {
    __shared__ float  xs[16][6][68];
    __shared__ float2 ws2[16][9][16];
    const float* __restrict__ src = (WHICH == 0) ? xin : (const float*)g_o65;
    float* dst = (WHICH == 0) ? g_h : g_o2;

    const int tid   = threadIdx.x;
    const int row_t = tid >> 6;          // 0..3
    const int rest  = tid & 63;
    const int cg    = rest & 3;          // co lane
    const int wg    = rest >> 2;         // 0..15 (4 w each)
    const int y0    = blockIdx.y * 4;
    const int b     = blockIdx.z;
    const int co0   = blockIdx.x * 16;

    u64 acc2[4][2];
    #pragma unroll
    for (int k = 0; k < 4; k++) { acc2[k][0] = pk2(0.f, 0.f); acc2[k][1] = pk2(0.f, 0.f); }

    const int NCH = (CI + 15) / 16;
    for (int cc = 0; cc < NCH; cc++) {
        int c0 = cc * 16;
        __syncthreads();
        for (int l = tid; l < 16 * 6 * 66; l += 256) {
            int ci = l / 396; int rem = l - ci * 396;
            int r = rem / 66; int wp = rem - r * 66;
            int hg = y0 - 1 + r;
            float v = 0.f;
            if (hg >= 0 && hg < 32 && wp >= 1 && wp <= 64 && (c0 + ci) < CI)
                v = src[(((b * CI + c0 + ci) << 5) + hg) * 64 + wp - 1];
            xs[ci][r][wp] = v;
        }
        for (int l = tid; l < 16 * 9 * 16; l += 256) {
            int col = l & 15; int t2 = l >> 4;
            int kk = t2 % 9;  int ci = t2 / 9;
            float v = 0.f;
            if ((co0 + col) < CO && (c0 + ci) < CI)
                v = wt[((co0 + col) * CI + c0 + ci) * 9 + kk];
            ws2[ci][kk][col] = make_float2(v, v);
        }
        __syncthreads();
        #pragma unroll 2
        for (int ci = 0; ci < 16; ci++) {
            #pragma unroll
            for (int r = 0; r < 3; r++) {
                const float* xr = &xs[ci][row_t + r][wg * 4];
                float4 xq = *reinterpret_cast<const float4*>(xr);
                float xv4 = xr[4], xv5 = xr[5];
                u64 P0 = pk2(xq.x, xq.y), P1 = pk2(xq.y, xq.z), P2 = pk2(xq.z, xq.w);
                u64 P3 = pk2(xq.w, xv4),  P4 = pk2(xv4, xv5);
                #pragma unroll
                for (int k = 0; k < 4; k++) {
                    u64 w0 = *reinterpret_cast<const u64*>(&ws2[ci][r * 3 + 0][cg + 4 * k]);
                    u64 w1 = *reinterpret_cast<const u64*>(&ws2[ci][r * 3 + 1][cg + 4 * k]);
                    u64 w2 = *reinterpret_cast<const u64*>(&ws2[ci][r * 3 + 2][cg + 4 * k]);
                    fm2(acc2[k][0], P0, w0); fm2(acc2[k][0], P1, w1); fm2(acc2[k][0], P2, w2);
                    fm2(acc2[k][1], P2, w0); fm2(acc2[k][1], P3, w1); fm2(acc2[k][1], P4, w2);
                }
            }
        }
    }
    #pragma unroll
    for (int k = 0; k < 4; k++) {
        int co = co0 + cg + 4 * k;
        if (co < CO) {
            float bs = bias[co];
            float4 o;
            upk2(o.x, o.y, acc2[k][0]);
            upk2(o.z, o.w, acc2[k][1]);
            o.x += bs; o.y += bs; o.z += bs; o.w += bs;
            *reinterpret_cast<float4*>(&dst[(((b * CO + co) << 5) + (y0 + row_t)) * 64 + wg * 4]) = o;
        }
    }
}

// ---------------- BN stats (block per channel) ----------------
template <int C, int WHICH>
__global__ void k_bnstats() {
    const float* src = (WHICH == 0) ? g_h : g_o2;
    int c = blockIdx.x;
    float s = 0.f, s2 = 0.f;
    for (int e = threadIdx.x; e < 16384; e += 256) {
        int b = e >> 11, j = e & 2047;
        float v = src[((b * C + c) << 11) + j];
        s += v; s2 += v * v;
    }
    __shared__ float sh[16];
    #pragma unroll
    for (int o = 16; o; o >>= 1) {
        s  += __shfl_xor_sync(0xffffffffu, s, o);
        s2 += __shfl_xor_sync(0xffffffffu, s2, o);
    }
    int lane = threadIdx.x & 31, wid = threadIdx.x >> 5;
    if (lane == 0) { sh[wid] = s; sh[8 + wid] = s2; }
    __syncthreads();
    if (threadIdx.x == 0) {
        float a = sh[0], b2 = sh[8];
        #pragma unroll
        for (int k = 1; k < 8; k++) { a += sh[k]; b2 += sh[8 + k]; }
        float m = a * (1.f / 16384.f);
        float var = b2 * (1.f / 16384.f) - m * m;
        if (WHICH == 0) { g_m65[c] = m;  g_is65[c] = rsqrtf(var + 1e-5f); }
        else            { g_m256[c] = m; g_is256[c] = rsqrtf(var + 1e-5f); }
    }
}

// ---------------- BN apply + split + field min/max/sum (2 blocks/channel) ----------------
__global__ void k_bnapply(const float* gz, const float* bz, const float* gq, const float* bq,
                          const float* gu, const float* bu, const float* gv, const float* bv,
                          const float* gt, const float* bt) {
    int c    = blockIdx.x >> 1;            // 0..64
    int part = blockIdx.x & 1;             // half of the channel
    int F = c / 13, v = c % 13;
    const float* ga = F == 0 ? gz : F == 1 ? gq : F == 2 ? gu : F == 3 ? gv : gt;
    const float* be = F == 0 ? bz : F == 1 ? bq : F == 2 ? bu : F == 3 ? bv : bt;
    float gsc = g_is65[c] * ga[v];
    float m   = g_m65[c];
    float bia = be[v];
    float inf = __int_as_float(0x7f800000);
    float mn = inf, mx = -inf, sm = 0.f;
    for (int e = part * 8192 + threadIdx.x; e < part * 8192 + 8192; e += 256) {
        int b = e >> 11, hw = e & 2047;
        float val = (g_h[((b * 65 + c) << 11) + hw] - m) * gsc + bia;
        g_fld[F][((b * 13 + v) << 11) + hw] = val;
        mn = fminf(mn, val); mx = fmaxf(mx, val); sm += val;
    }
    blockRed(mn, mx, sm, F, 5 + F, 10 + F);
}

// ---------------- base derivs (z,u,v,t,q) + sarg reduce ----------------
__global__ void k_basederiv() {
    float inf = __int_as_float(0x7f800000);
    float smn = inf, smx = -inf;
    for (int i = blockIdx.x * 256 + threadIdx.x; i < NFE; i += GSB * 256) {
        Pos p = decodeP(i);
        g_zx[i] = dxf(g_fld[0], p);
        g_zy[i] = dyf(g_fld[0], p);
        g_zz[i] = dzf(g_fld[0], p);
        float ux = dxf(g_fld[2], p);
        float vy = dyf(g_fld[3], p);
        g_ax[i] = ux;  g_ux[i] = ux;
        g_ay[i] = dyf(g_fld[2], p);
        g_az[i] = dzf(g_fld[2], p);
        g_bx[i] = dxf(g_fld[3], p);
        g_by[i] = vy;  g_vy[i] = vy;
        g_bz[i] = dzf(g_fld[3], p);
        g_cx[i] = dxf(g_fld[4], p);
        g_cy[i] = dyf(g_fld[4], p);
        g_cz[i] = dzf(g_fld[4], p);
        g_qx[i] = dxf(g_fld[1], p);
        g_qy[i] = dyf(g_fld[1], p);
        g_qz[i] = dzf(g_fld[1], p);
        float tc = g_fld[4][i] - 273.15f;
        float s = 17.67f * tc / avoid_inf1(tc + 243.5f);
        smn = fminf(smn, s); smx = fmaxf(smx, s);
    }
    blockRed(smn, smx, 0.f, 15, 16, -1);
}

// ---------------- w_vel column integral ----------------
__global__ void k_wvel() {
    int j = blockIdx.x * 256 + threadIdx.x;       // 16384 columns
    int b = j >> 11, hw = j & 2047;
    float s = 0.f;
    for (int v = 0; v < 13; v++) {
        int off = ((b * 13 + v) << 11) + hw;
        s += c_DZ[v] * (g_ux[off] + g_vy[off]);
        g_w[off] = -s;
    }
}

// ---------------- saturation + precip rate ----------------
__global__ void k_qs() {
    int i = blockIdx.x * 256 + threadIdx.x;
    float zz = g_zz[i];
    float tt = g_fld[4][i];
    float q  = g_fld[1][i];
    float rho = -1.f / avoid_inf1(zz);
    float pr  = rho * RGASc * tt;
    float tc  = tt - 273.15f;
    float s   = 17.67f * tc / avoid_inf1(tc + 243.5f);
    float smn = g_red[15], smx = g_red[16];
    float sc  = (s - smn) / (smx - smn) * 6.48f - 3.47f;
    float es  = 6.112f * expf(sc) * 100.f;
    float qs  = fmaxf(0.622f * es / avoid_inf1(pr - 0.378f * es), 1e-6f);
    float rh  = q / avoid_inf1(qs);
    g_rate[i] = (rh > 0.8f) ? (q - 0.8f * qs) * (1.f / DTs) : 0.f;
}

// ---------------- derivatives of stage fields u,v,t ----------------
__global__ void k_derivAll() {
    int i = blockIdx.x * 256 + threadIdx.x;
    Pos p = decodeP(i);
    g_ax[i] = dxf(g_sua, p); g_ay[i] = dyf(g_sua, p); g_az[i] = dzf(g_sua, p);
    g_bx[i] = dxf(g_sva, p); g_by[i] = dyf(g_sva, p); g_bz[i] = dzf(g_sva, p);
    g_cx[i] = dxf(g_sta, p); g_cy[i] = dyf(g_sta, p); g_cz[i] = dzf(g_sta, p);
}

// ---------------- combined RK stage for u,v,t (+q tendency at stage 0) ----------------
__global__ void k_stage(int stage) {
    float inf = __int_as_float(0x7f800000);
    float umn = inf, umx = -inf, vmn = inf, vmx = -inf, tmn = inf, tmx = -inf;
    float qmn = inf, qmx = -inf;
    for (int i = blockIdx.x * 256 + threadIdx.x; i < NFE; i += GSB * 256) {
        Pos p = decodeP(i);
        float w  = g_w[i];
        float zz = g_zz[i];
        float f  = g_fcor[p.h];
        float u0 = g_fld[2][i], v0 = g_fld[3][i], t0 = g_fld[4][i];
        float uai = stage == 0 ? u0 : g_sua[i];
        float vai = stage == 0 ? v0 : g_sva[i];
        float tai = stage == 0 ? t0 : g_sta[i];

        float dxx_u = dxf(g_ax, p), dyy_u = dyf(g_ay, p), dzz_u = dzf(g_az, p);
        float dxx_v = dxf(g_bx, p), dyy_v = dyf(g_by, p), dzz_v = dzf(g_bz, p);
        float dxx_t = dxf(g_cx, p), dyy_t = dyf(g_cy, p), dzz_t = dzf(g_cz, p);

        float ku = -uai * g_ux[i] - vai * g_ay[i] - w * g_az[i] + f * vai - g_zx[i]
                 + KHc * (dxx_u + dyy_u) + KVc * dzz_u;
        float kv = -uai * g_bx[i] - vai * g_vy[i] - w * g_bz[i] - f * uai - g_zy[i]
                 + KHc * (dxx_v + dyy_v) + KVc * dzz_v;

        float taabs = tai + 273.15f;
        float t2 = taabs * taabs;
        float t5 = t2 * t2 * taabs;
        float rc = -(EMISc * SIGMAc * RDc / (CPc * 100.f)) * t5 / c_PRS[p.v];
        float lh = g_rate[i] * (LVc / CPc);
        float kt = -((LVc + 1.f) / CPc) * zz * w - u0 * g_cx[i] - v0 * g_cy[i] - w * g_cz[i]
                 + KHc * (dxx_t + dyy_t) + KVc * dzz_t + rc + lh;

        if (stage == 0) {
            g_accu[i] = ku; g_accv[i] = kv; g_acct[i] = kt;
            g_sua[i] = u0 + 0.5f * DTs * ku;
            g_sva[i] = v0 + 0.5f * DTs * kv;
            g_sta[i] = t0 + 0.5f * DTs * kt;
            // q tendency (base derivs still in g_qx..): mixing + advection - rate
            float dxx_q = dxf(g_qx, p), dyy_q = dyf(g_qy, p), dzz_q = dzf(g_qz, p);
            float qt = -u0 * g_qx[i] - v0 * g_qy[i] - w * g_qz[i]
                     + KHc * (dxx_q + dyy_q) + KVc * dzz_q - g_rate[i];
            float dq = qt * DTs;
            g_dq[i] = dq;
            qmn = fminf(qmn, dq); qmx = fmaxf(qmx, dq);
        } else if (stage == 1) {
            g_accu[i] += 2.f * ku; g_accv[i] += 2.f * kv; g_acct[i] += 2.f * kt;
            g_sua[i] = u0 + 0.5f * DTs * ku;
            g_sva[i] = v0 + 0.5f * DTs * kv;
            g_sta[i] = t0 + 0.5f * DTs * kt;
        } else if (stage == 2) {
            g_accu[i] += 2.f * ku; g_accv[i] += 2.f * kv; g_acct[i] += 2.f * kt;
            g_sua[i] = u0 + DTs * ku;
            g_sva[i] = v0 + DTs * kv;
            g_sta[i] = t0 + DTs * kt;
        } else {
            g_k4t[i] = kt;
            float du = (g_accu[i] + ku) * (DTs / 6.f);
            float dv = (g_accv[i] + kv) * (DTs / 6.f);
            float dt_ = (g_acct[i] + kt) * (DTs / 6.f);
            g_accu[i] = du; g_accv[i] = dv; g_acct[i] = dt_;
            umn = fminf(umn, du); umx = fmaxf(umx, du);
            vmn = fminf(vmn, dv); vmx = fmaxf(vmx, dv);
            tmn = fminf(tmn, dt_); tmx = fmaxf(tmx, dt_);
        }
    }
    if (stage == 0) {
        blockRed(qmn, qmx, 0.f, 18, 23, -1);
    } else if (stage == 3) {
        blockRed(umn, umx, 0.f, 19, 24, -1);
        blockRed(vmn, vmx, 0.f, 20, 25, -1);
        blockRed(tmn, tmx, 0.f, 21, 26, -1);
    }
}

// ---------------- z tendency column integral ----------------
__global__ void k_zt() {
    int j = blockIdx.x * 256 + threadIdx.x;       // 16384 columns
    int b = j >> 11, hw = j & 2047;
    float s = 0.f;
    float inf = __int_as_float(0x7f800000);
    float mn = inf, mx = -inf;
    for (int v = 0; v < 13; v++) {
        int off = ((b * 13 + v) << 11) + hw;
        s += c_DZ[v] * (-RGASc / c_PRS[v]) * g_k4t[off];
        float d = s * DTs;
        g_dzd[off] = d;
        mn = fminf(mn, d); mx = fmaxf(mx, d);
    }
    blockRed(mn, mx, 0.f, 17, 22, -1);
}

// ---------------- apply scale_diff + coef mix -> g_o65 ----------------
__global__ void k_apply65(const float* __restrict__ coef) {
    int i = blockIdx.x * 256 + threadIdx.x;
    int bc = i >> 11;
    int c = bc % 65, b = bc / 65;
    int hw = i & 2047;
    int F = c / 13, v = c % 13;
    int fi = ((b * 13 + v) << 11) + hw;
    float base = g_fld[F][fi];
    float diff = F == 0 ? g_dzd[fi] : F == 1 ? g_dq[fi] :
                 F == 2 ? g_accu[fi] : F == 3 ? g_accv[fi] : g_acct[fi];
    float mn = g_red[F], mx = g_red[5 + F];
    float me = g_red[10 + F] * (1.f / 212992.f);
    float a = (mn - me) * 0.05f;
    float bb = (mx - me) * 0.05f;
    float dmn = g_red[17 + F], dmx = g_red[22 + F];
    float nv = base + (diff - dmn) / (dmx - dmn) * (bb - a) + a;
    float cf = coef[(c << 11) + hw];
    g_o65[i] = cf * nv + (1.f - cf) * g_h[i];
}

// ---------------- final: BN(o2) + x ----------------
__global__ void k_final(const float* __restrict__ x, const float* __restrict__ gblk,
                        const float* __restrict__ bblk, float* __restrict__ out) {
    int i = blockIdx.x * 256 + threadIdx.x;
    int c = (i >> 11) & 255;
    out[i] = (g_o2[i] - g_m256[c]) * g_is256[c] * gblk[c] + bblk[c] + x[i];
}

// ---------------- launcher ----------------
extern "C" void kernel_launch(void* const* d_in, const int* in_sizes, int n_in,
                              void* d_out, int out_size) {
    const float* x        = (const float*)d_in[0];
    const float* w_norm   = (const float*)d_in[1];
    const float* b_norm   = (const float*)d_in[2];
    const float* w_innorm = (const float*)d_in[3];
    const float* b_innorm = (const float*)d_in[4];
    const float* coef     = (const float*)d_in[5];
    const float* gz = (const float*)d_in[6];  const float* bz = (const float*)d_in[7];
    const float* gq = (const float*)d_in[8];  const float* bq = (const float*)d_in[9];
    const float* gu = (const float*)d_in[10]; const float* bu = (const float*)d_in[11];
    const float* gv = (const float*)d_in[12]; const float* bv = (const float*)d_in[13];
    const float* gt = (const float*)d_in[14]; const float* bt = (const float*)d_in[15];
    const float* gblk = (const float*)d_in[16];
    const float* bblk = (const float*)d_in[17];
    float* out = (float*)d_out;

    const int GF = NFE / 256;      // 832

    k_init<<<1, 64>>>();
    k_conv<256, 65, 0><<<dim3(5, 8, 8), 256>>>(x, w_norm, b_norm);
    k_bnstats<65, 0><<<65, 256>>>();
    k_bnapply<<<130, 256>>>(gz, bz, gq, bq, gu, bu, gv, bv, gt, bt);
    k_basederiv<<<GSB, 256>>>();
    k_wvel<<<64, 256>>>();
    k_qs<<<GF, 256>>>();
    k_stage<<<GSB, 256>>>(0);
    for (int s = 1; s < 4; s++) {
        k_derivAll<<<GF, 256>>>();
        k_stage<<<GSB, 256>>>(s);
    }
    k_zt<<<64, 256>>>();
    k_apply65<<<NHE / 256, 256>>>(coef);
    k_conv<65, 256, 1><<<dim3(16, 8, 8), 256>>>(nullptr, w_innorm, b_innorm);
    k_bnstats<256, 1><<<256, 256>>>();
    k_final<<<NOE / 256, 256>>>(x, gblk, bblk, out);
}

// round 5
// speedup vs baseline: 1.0516x; 1.0516x over previous
#include <cuda_runtime.h>
#include <math.h>

// ---------------- dims ----------------
#define NFE 212992              // 8*13*32*64
#define NHE 1064960             // 8*65*32*64
#define NOE 4194304             // 8*256*32*64

// ---------------- physics consts ----------------
#define DTs    300.0f
#define KHc    15.0f
#define KVc    0.1f
#define LVc    2.5e6f
#define CPc    1005.0f
#define RGASc  8.314f
#define RDc    287.0f
#define OMEGAc 7.29e-5f
#define EMISc  0.7f
#define SIGMAc 5.67e-8f
#define PIXYc  ((float)(M_PI * 6371000.0 / 33.0))

__constant__ float c_DZ[13]  = {50.f,50.f,50.f,50.f,50.f,75.f,100.f,100.f,100.f,125.f,112.f,75.f,75.f};
__constant__ float c_PRS[13] = {50.f,100.f,150.f,200.f,250.f,300.f,400.f,500.f,600.f,700.f,850.f,925.f,1000.f};

// ---------------- scratch ----------------
__device__ float g_h[NHE], g_o65[NHE];
__device__ float g_o2[NOE];
__device__ float g_fld[5][NFE];                        // z,q,u,v,t post-BN
__device__ float g_zx[NFE], g_zy[NFE], g_zz[NFE], g_ux[NFE], g_vy[NFE];
__device__ float g_w[NFE], g_rate[NFE];
__device__ float g_sua[NFE], g_sva[NFE], g_sta[NFE];   // RK stage fields u,v,t
__device__ float g_ax[NFE], g_ay[NFE], g_az[NFE];      // u-stage derivs
__device__ float g_bx[NFE], g_by[NFE], g_bz[NFE];      // v-stage derivs
__device__ float g_cx[NFE], g_cy[NFE], g_cz[NFE];      // t-stage derivs
__device__ float g_qx[NFE], g_qy[NFE], g_qz[NFE];      // base q derivs
__device__ float g_accu[NFE], g_accv[NFE], g_acct[NFE];
__device__ float g_k4t[NFE], g_dq[NFE], g_dzd[NFE];
__device__ float g_m65[65], g_is65[65], g_m256[256], g_is256[256];
__device__ float g_red[27];
__device__ float g_invpx[32], g_fcor[32];

// red slots: 0..4 field min (z,q,u,v,t); 5..9 field max; 10..14 field sum;
//            15 sarg min; 16 sarg max; 17..21 diff min (z,q,u,v,t); 22..26 diff max

// ---------------- helpers ----------------
__device__ __forceinline__ void atomicMinF(float* a, float v) {
    if (v >= 0.f) atomicMin((int*)a, __float_as_int(v));
    else          atomicMax((unsigned int*)a, __float_as_uint(v));
}
__device__ __forceinline__ void atomicMaxF(float* a, float v) {
    if (v >= 0.f) atomicMax((int*)a, __float_as_int(v));
    else          atomicMin((unsigned int*)a, __float_as_uint(v));
}
__device__ __forceinline__ float avoid_inf1(float t) {
    if (t == 0.f) return 1.f;
    if (fabsf(t) < 1.f) return t > 0.f ? 1.f : -1.f;
    return t;
}

typedef unsigned long long u64;
__device__ __forceinline__ u64 pk2(float lo, float hi) {
    u64 r; asm("mov.b64 %0,{%1,%2};" : "=l"(r) : "f"(lo), "f"(hi)); return r;
}
__device__ __forceinline__ void fm2(u64& d, u64 a, u64 b) {
    asm("fma.rn.f32x2 %0,%1,%2,%0;" : "+l"(d) : "l"(a), "l"(b));
}
__device__ __forceinline__ void upk2(float& lo, float& hi, u64 v) {
    asm("mov.b64 {%0,%1},%2;" : "=f"(lo), "=f"(hi) : "l"(v));
}

struct Pos { int b, v, h, w, i; };
__device__ __forceinline__ Pos decodeP(int i) {
    Pos p; p.i = i; p.w = i & 63; p.h = (i >> 6) & 31;
    int bv = i >> 11; p.v = bv % 13; p.b = bv / 13;
    return p;
}
__device__ __forceinline__ int pidxN(int m, int n) {   // block-replicate pad index
    return m < 2 ? m : (m < n + 2 ? m - 2 : m - 4);
}
__device__ __forceinline__ float dxf(const float* __restrict__ f, const Pos& p) {
    int base = p.i - p.w;
    float g = (f[base + ((p.w + 62) & 63)] - 8.f * f[base + ((p.w + 63) & 63)]
             + 8.f * f[base + ((p.w + 1) & 63)] - f[base + ((p.w + 2) & 63)]) * (1.f / 12.f);
    return g * g_invpx[p.h];
}
__device__ __forceinline__ float dyf(const float* __restrict__ f, const Pos& p) {
    int base = p.i - (p.h << 6);
    float g = (-f[base + (pidxN(p.h, 32) << 6)] + 8.f * f[base + (pidxN(p.h + 1, 32) << 6)]
             - 8.f * f[base + (pidxN(p.h + 3, 32) << 6)] + f[base + (pidxN(p.h + 4, 32) << 6)]) * (1.f / 12.f);
    return g * (1.f / PIXYc);
}
__device__ __forceinline__ float dzf(const float* __restrict__ f, const Pos& p) {
    int base = p.i - (p.v << 11);
    float g = (-f[base + (pidxN(p.v, 13) << 11)] + 8.f * f[base + (pidxN(p.v + 1, 13) << 11)]
             - 8.f * f[base + (pidxN(p.v + 3, 13) << 11)] + f[base + (pidxN(p.v + 4, 13) << 11)]) * (1.f / 12.f);
    return g / c_DZ[p.v];
}

// block reduction (blockDim == 256) -> atomics to g_red; ssum<0 skips sum
__device__ __forceinline__ void blockRed(float vmn, float vmx, float vsum,
                                         int smn, int smx, int ssum) {
    __shared__ float sh[24];
    __syncthreads();
    #pragma unroll
    for (int o = 16; o; o >>= 1) {
        vmn  = fminf(vmn, __shfl_xor_sync(0xffffffffu, vmn, o));
        vmx  = fmaxf(vmx, __shfl_xor_sync(0xffffffffu, vmx, o));
        vsum += __shfl_xor_sync(0xffffffffu, vsum, o);
    }
    int lane = threadIdx.x & 31, wid = threadIdx.x >> 5;
    if (lane == 0) { sh[wid] = vmn; sh[8 + wid] = vmx; sh[16 + wid] = vsum; }
    __syncthreads();
    if (threadIdx.x == 0) {
        float a = sh[0], b = sh[8], s = sh[16];
        #pragma unroll
        for (int k = 1; k < 8; k++) { a = fminf(a, sh[k]); b = fmaxf(b, sh[8 + k]); s += sh[16 + k]; }
        atomicMinF(&g_red[smn], a);
        atomicMaxF(&g_red[smx], b);
        if (ssum >= 0) atomicAdd(&g_red[ssum], s);
    }
}

// min/max-only block reduction for up to 3 pairs in one pass (fewer barriers)
__device__ __forceinline__ void blockRed3(float mn0, float mx0, float mn1, float mx1,
                                          float mn2, float mx2, int s0, int s1, int s2) {
    __shared__ float sh[48];
    __syncthreads();
    #pragma unroll
    for (int o = 16; o; o >>= 1) {
        mn0 = fminf(mn0, __shfl_xor_sync(0xffffffffu, mn0, o));
        mx0 = fmaxf(mx0, __shfl_xor_sync(0xffffffffu, mx0, o));
        mn1 = fminf(mn1, __shfl_xor_sync(0xffffffffu, mn1, o));
        mx1 = fmaxf(mx1, __shfl_xor_sync(0xffffffffu, mx1, o));
        mn2 = fminf(mn2, __shfl_xor_sync(0xffffffffu, mn2, o));
        mx2 = fmaxf(mx2, __shfl_xor_sync(0xffffffffu, mx2, o));
    }
    int lane = threadIdx.x & 31, wid = threadIdx.x >> 5;
    if (lane == 0) {
        sh[wid] = mn0; sh[8 + wid] = mx0; sh[16 + wid] = mn1;
        sh[24 + wid] = mx1; sh[32 + wid] = mn2; sh[40 + wid] = mx2;
    }
    __syncthreads();
    if (threadIdx.x == 0) {
        float a0 = sh[0], b0 = sh[8], a1 = sh[16], b1 = sh[24], a2 = sh[32], b2 = sh[40];
        #pragma unroll
        for (int k = 1; k < 8; k++) {
            a0 = fminf(a0, sh[k]);      b0 = fmaxf(b0, sh[8 + k]);
            a1 = fminf(a1, sh[16 + k]); b1 = fmaxf(b1, sh[24 + k]);
            a2 = fminf(a2, sh[32 + k]); b2 = fmaxf(b2, sh[40 + k]);
        }
        atomicMinF(&g_red[s0], a0); atomicMaxF(&g_red[s0 + 5], b0);
        atomicMinF(&g_red[s1], a1); atomicMaxF(&g_red[s1 + 5], b1);
        atomicMinF(&g_red[s2], a2); atomicMaxF(&g_red[s2 + 5], b2);
    }
}

// ---------------- init ----------------
__global__ void k_init() {
    int t = threadIdx.x;
    if (t < 32) {
        double lat = (90.0 - (double)(t + 1) * (180.0 / 33.0)) * M_PI / 180.0;
        float px = (float)(2.0 * M_PI * 6371000.0 * cos(lat) / 64.0);
        g_invpx[t] = 1.f / px;
        g_fcor[t]  = 2.0f * OMEGAc * sinf((float)lat);
    }
    if (t < 27) {
        float inf = __int_as_float(0x7f800000);
        float v;
        if (t < 5) v = inf;
        else if (t < 10) v = -inf;
        else if (t < 15) v = 0.f;
        else if (t == 15) v = inf;
        else if (t == 16) v = -inf;
        else if (t < 22) v = inf;
        else v = -inf;
        g_red[t] = v;
    }
}

// ---------------- conv3x3 zero-pad (cross-correlation), f32x2 inner ----------------
template <int CI, int CO, int WHICH>
__global__ void __launch_bounds__(256) k_conv(const float* __restrict__ xin,
                                              const float* __restrict__ wt,
                                              const float* __restrict__ bias) {
    __shared__ float  xs[16][6][68];
    __shared__ float2 ws2[16][9][16];
    const float* __restrict__ src = (WHICH == 0) ? xin : (const float*)g_o65;
    float* dst = (WHICH == 0) ? g_h : g_o2;

    const int tid   = threadIdx.x;
    const int row_t = tid >> 6;          // 0..3
    const int rest  = tid & 63;
    const int cg    = rest & 3;          // co lane
    const int wg    = rest >> 2;         // 0..15 (4 w each)
    const int y0    = blockIdx.y * 4;
    const int b     = blockIdx.z;
    const int co0   = blockIdx.x * 16;

    u64 acc2[4][2];
    #pragma unroll
    for (int k = 0; k < 4; k++) { acc2[k][0] = pk2(0.f, 0.f); acc2[k][1] = pk2(0.f, 0.f); }

    const int NCH = (CI + 15) / 16;
    for (int cc = 0; cc < NCH; cc++) {
        int c0 = cc * 16;
        __syncthreads();
        for (int l = tid; l < 16 * 6 * 66; l += 256) {
            int ci = l / 396; int rem = l - ci * 396;
            int r = rem / 66; int wp = rem - r * 66;
            int hg = y0 - 1 + r;
            float v = 0.f;
            if (hg >= 0 && hg < 32 && wp >= 1 && wp <= 64 && (c0 + ci) < CI)
                v = src[(((b * CI + c0 + ci) << 5) + hg) * 64 + wp - 1];
            xs[ci][r][wp] = v;
        }
        for (int l = tid; l < 16 * 9 * 16; l += 256) {
            int col = l & 15; int t2 = l >> 4;
            int kk = t2 % 9;  int ci = t2 / 9;
            float v = 0.f;
            if ((co0 + col) < CO && (c0 + ci) < CI)
                v = wt[((co0 + col) * CI + c0 + ci) * 9 + kk];
            ws2[ci][kk][col] = make_float2(v, v);
        }
        __syncthreads();
        #pragma unroll 2
        for (int ci = 0; ci < 16; ci++) {
            #pragma unroll
            for (int r = 0; r < 3; r++) {
                const float* xr = &xs[ci][row_t + r][wg * 4];
                float4 xq = *reinterpret_cast<const float4*>(xr);
                float xv4 = xr[4], xv5 = xr[5];
                u64 P0 = pk2(xq.x, xq.y), P1 = pk2(xq.y, xq.z), P2 = pk2(xq.z, xq.w);
                u64 P3 = pk2(xq.w, xv4),  P4 = pk2(xv4, xv5);
                #pragma unroll
                for (int k = 0; k < 4; k++) {
                    u64 w0 = *reinterpret_cast<const u64*>(&ws2[ci][r * 3 + 0][cg + 4 * k]);
                    u64 w1 = *reinterpret_cast<const u64*>(&ws2[ci][r * 3 + 1][cg + 4 * k]);
                    u64 w2 = *reinterpret_cast<const u64*>(&ws2[ci][r * 3 + 2][cg + 4 * k]);
                    fm2(acc2[k][0], P0, w0); fm2(acc2[k][0], P1, w1); fm2(acc2[k][0], P2, w2);
                    fm2(acc2[k][1], P2, w0); fm2(acc2[k][1], P3, w1); fm2(acc2[k][1], P4, w2);
                }
            }
        }
    }
    #pragma unroll
    for (int k = 0; k < 4; k++) {
        int co = co0 + cg + 4 * k;
        if (co < CO) {
            float bs = bias[co];
            float4 o;
            upk2(o.x, o.y, acc2[k][0]);
            upk2(o.z, o.w, acc2[k][1]);
            o.x += bs; o.y += bs; o.z += bs; o.w += bs;
            *reinterpret_cast<float4*>(&dst[(((b * CO + co) << 5) + (y0 + row_t)) * 64 + wg * 4]) = o;
        }
    }
}

// ---------------- BN stats (block per channel) ----------------
template <int C, int WHICH>
__global__ void k_bnstats() {
    const float* src = (WHICH == 0) ? g_h : g_o2;
    int c = blockIdx.x;
    float s = 0.f, s2 = 0.f;
    for (int e = threadIdx.x; e < 4096; e += 256) {
        int b = e >> 9, j = (e & 511) << 2;
        float4 v4 = *reinterpret_cast<const float4*>(&src[((b * C + c) << 11) + j]);
        s  += v4.x + v4.y + v4.z + v4.w;
        s2 += v4.x * v4.x + v4.y * v4.y + v4.z * v4.z + v4.w * v4.w;
    }
    __shared__ float sh[16];
    #pragma unroll
    for (int o = 16; o; o >>= 1) {
        s  += __shfl_xor_sync(0xffffffffu, s, o);
        s2 += __shfl_xor_sync(0xffffffffu, s2, o);
    }
    int lane = threadIdx.x & 31, wid = threadIdx.x >> 5;
    if (lane == 0) { sh[wid] = s; sh[8 + wid] = s2; }
    __syncthreads();
    if (threadIdx.x == 0) {
        float a = sh[0], b2 = sh[8];
        #pragma unroll
        for (int k = 1; k < 8; k++) { a += sh[k]; b2 += sh[8 + k]; }
        float m = a * (1.f / 16384.f);
        float var = b2 * (1.f / 16384.f) - m * m;
        if (WHICH == 0) { g_m65[c] = m;  g_is65[c] = rsqrtf(var + 1e-5f); }
        else            { g_m256[c] = m; g_is256[c] = rsqrtf(var + 1e-5f); }
    }
}

// ---------------- BN apply + split + field min/max/sum (float4, grid 1040) ----------------
__global__ void k_bnapply(const float* gz, const float* bz, const float* gq, const float* bq,
                          const float* gu, const float* bu, const float* gv, const float* bv,
                          const float* gt, const float* bt) {
    int i4 = blockIdx.x * 256 + threadIdx.x;
    int i  = i4 << 2;
    int bc = i >> 11;
    int c = bc % 65, b = bc / 65;
    int hw = i & 2047;
    int F = c / 13, v = c % 13;
    const float* ga = F == 0 ? gz : F == 1 ? gq : F == 2 ? gu : F == 3 ? gv : gt;
    const float* be = F == 0 ? bz : F == 1 ? bq : F == 2 ? bu : F == 3 ? bv : bt;
    float gsc = g_is65[c] * ga[v];
    float m   = g_m65[c];
    float bia = be[v];
    float4 hv = *reinterpret_cast<const float4*>(&g_h[i]);
    float4 o;
    o.x = (hv.x - m) * gsc + bia; o.y = (hv.y - m) * gsc + bia;
    o.z = (hv.z - m) * gsc + bia; o.w = (hv.w - m) * gsc + bia;
    *reinterpret_cast<float4*>(&g_fld[F][((b * 13 + v) << 11) + hw]) = o;
    float mn = fminf(fminf(o.x, o.y), fminf(o.z, o.w));
    float mx = fmaxf(fmaxf(o.x, o.y), fmaxf(o.z, o.w));
    float sm = o.x + o.y + o.z + o.w;
    blockRed(mn, mx, sm, F, 5 + F, 10 + F);
}

// ---------------- base derivs (z,u,v,t,q) + sarg reduce (832 blocks) ----------------
__global__ void k_basederiv() {
    int i = blockIdx.x * 256 + threadIdx.x;
    Pos p = decodeP(i);
    g_zx[i] = dxf(g_fld[0], p);
    g_zy[i] = dyf(g_fld[0], p);
    g_zz[i] = dzf(g_fld[0], p);
    float ux = dxf(g_fld[2], p);
    float vy = dyf(g_fld[3], p);
    g_ax[i] = ux;  g_ux[i] = ux;
    g_ay[i] = dyf(g_fld[2], p);
    g_az[i] = dzf(g_fld[2], p);
    g_bx[i] = dxf(g_fld[3], p);
    g_by[i] = vy;  g_vy[i] = vy;
    g_bz[i] = dzf(g_fld[3], p);
    g_cx[i] = dxf(g_fld[4], p);
    g_cy[i] = dyf(g_fld[4], p);
    g_cz[i] = dzf(g_fld[4], p);
    g_qx[i] = dxf(g_fld[1], p);
    g_qy[i] = dyf(g_fld[1], p);
    g_qz[i] = dzf(g_fld[1], p);
    float tc = g_fld[4][i] - 273.15f;
    float s = 17.67f * tc / avoid_inf1(tc + 243.5f);
    blockRed(s, s, 0.f, 15, 16, -1);
}

// ---------------- w_vel column integral ----------------
__global__ void k_wvel() {
    int j = blockIdx.x * 128 + threadIdx.x;       // 16384 columns
    int b = j >> 11, hw = j & 2047;
    float s = 0.f;
    for (int v = 0; v < 13; v++) {
        int off = ((b * 13 + v) << 11) + hw;
        s += c_DZ[v] * (g_ux[off] + g_vy[off]);
        g_w[off] = -s;
    }
}

// ---------------- saturation + precip rate ----------------
__global__ void k_qs() {
    int i = blockIdx.x * 256 + threadIdx.x;
    float zz = g_zz[i];
    float tt = g_fld[4][i];
    float q  = g_fld[1][i];
    float rho = -1.f / avoid_inf1(zz);
    float pr  = rho * RGASc * tt;
    float tc  = tt - 273.15f;
    float s   = 17.67f * tc / avoid_inf1(tc + 243.5f);
    float smn = g_red[15], smx = g_red[16];
    float sc  = (s - smn) / (smx - smn) * 6.48f - 3.47f;
    float es  = 6.112f * expf(sc) * 100.f;
    float qs  = fmaxf(0.622f * es / avoid_inf1(pr - 0.378f * es), 1e-6f);
    float rh  = q / avoid_inf1(qs);
    g_rate[i] = (rh > 0.8f) ? (q - 0.8f * qs) * (1.f / DTs) : 0.f;
}

// ---------------- derivatives of stage fields u,v,t ----------------
__global__ void k_derivAll() {
    int i = blockIdx.x * 256 + threadIdx.x;
    Pos p = decodeP(i);
    g_ax[i] = dxf(g_sua, p); g_ay[i] = dyf(g_sua, p); g_az[i] = dzf(g_sua, p);
    g_bx[i] = dxf(g_sva, p); g_by[i] = dyf(g_sva, p); g_bz[i] = dzf(g_sva, p);
    g_cx[i] = dxf(g_sta, p); g_cy[i] = dyf(g_sta, p); g_cz[i] = dzf(g_sta, p);
}

// ---------------- combined RK stage for u,v,t (+q tendency at stage 0) ----------------
__global__ void k_stage(int stage) {
    int i = blockIdx.x * 256 + threadIdx.x;
    Pos p = decodeP(i);
    float w  = g_w[i];
    float zz = g_zz[i];
    float f  = g_fcor[p.h];
    float u0 = g_fld[2][i], v0 = g_fld[3][i], t0 = g_fld[4][i];
    float uai = stage == 0 ? u0 : g_sua[i];
    float vai = stage == 0 ? v0 : g_sva[i];
    float tai = stage == 0 ? t0 : g_sta[i];

    float dxx_u = dxf(g_ax, p), dyy_u = dyf(g_ay, p), dzz_u = dzf(g_az, p);
    float dxx_v = dxf(g_bx, p), dyy_v = dyf(g_by, p), dzz_v = dzf(g_bz, p);
    float dxx_t = dxf(g_cx, p), dyy_t = dyf(g_cy, p), dzz_t = dzf(g_cz, p);

    float ku = -uai * g_ux[i] - vai * g_ay[i] - w * g_az[i] + f * vai - g_zx[i]
             + KHc * (dxx_u + dyy_u) + KVc * dzz_u;
    float kv = -uai * g_bx[i] - vai * g_vy[i] - w * g_bz[i] - f * uai - g_zy[i]
             + KHc * (dxx_v + dyy_v) + KVc * dzz_v;

    float taabs = tai + 273.15f;
    float t2 = taabs * taabs;
    float t5 = t2 * t2 * taabs;
    float rc = -(EMISc * SIGMAc * RDc / (CPc * 100.f)) * t5 / c_PRS[p.v];
    float lh = g_rate[i] * (LVc / CPc);
    float kt = -((LVc + 1.f) / CPc) * zz * w - u0 * g_cx[i] - v0 * g_cy[i] - w * g_cz[i]
             + KHc * (dxx_t + dyy_t) + KVc * dzz_t + rc + lh;

    if (stage == 0) {
        g_accu[i] = ku; g_accv[i] = kv; g_acct[i] = kt;
        g_sua[i] = u0 + 0.5f * DTs * ku;
        g_sva[i] = v0 + 0.5f * DTs * kv;
        g_sta[i] = t0 + 0.5f * DTs * kt;
        float dxx_q = dxf(g_qx, p), dyy_q = dyf(g_qy, p), dzz_q = dzf(g_qz, p);
        float qt = -u0 * g_qx[i] - v0 * g_qy[i] - w * g_qz[i]
                 + KHc * (dxx_q + dyy_q) + KVc * dzz_q - g_rate[i];
        float dq = qt * DTs;
        g_dq[i] = dq;
        blockRed(dq, dq, 0.f, 18, 23, -1);
    } else if (stage == 1) {
        g_accu[i] += 2.f * ku; g_accv[i] += 2.f * kv; g_acct[i] += 2.f * kt;
        g_sua[i] = u0 + 0.5f * DTs * ku;
        g_sva[i] = v0 + 0.5f * DTs * kv;
        g_sta[i] = t0 + 0.5f * DTs * kt;
    } else if (stage == 2) {
        g_accu[i] += 2.f * ku; g_accv[i] += 2.f * kv; g_acct[i] += 2.f * kt;
        g_sua[i] = u0 + DTs * ku;
        g_sva[i] = v0 + DTs * kv;
        g_sta[i] = t0 + DTs * kt;
    } else {
        g_k4t[i] = kt;
        float du = (g_accu[i] + ku) * (DTs / 6.f);
        float dv = (g_accv[i] + kv) * (DTs / 6.f);
        float dt_ = (g_acct[i] + kt) * (DTs / 6.f);
        g_accu[i] = du; g_accv[i] = dv; g_acct[i] = dt_;
        blockRed3(du, du, dv, dv, dt_, dt_, 19, 20, 21);
    }
}

// ---------------- z tendency column integral ----------------
__global__ void k_zt() {
    int j = blockIdx.x * 128 + threadIdx.x;       // 16384 columns
    int b = j >> 11, hw = j & 2047;
    float s = 0.f;
    float inf = __int_as_float(0x7f800000);
    float mn = inf, mx = -inf;
    for (int v = 0; v < 13; v++) {
        int off = ((b * 13 + v) << 11) + hw;
        s += c_DZ[v] * (-RGASc / c_PRS[v]) * g_k4t[off];
        float d = s * DTs;
        g_dzd[off] = d;
        mn = fminf(mn, d); mx = fmaxf(mx, d);
    }
    // blockDim 128 here: do a manual 128-wide reduce via shuffles + shared
    __shared__ float sh[8];
    #pragma unroll
    for (int o = 16; o; o >>= 1) {
        mn = fminf(mn, __shfl_xor_sync(0xffffffffu, mn, o));
        mx = fmaxf(mx, __shfl_xor_sync(0xffffffffu, mx, o));
    }
    int lane = threadIdx.x & 31, wid = threadIdx.x >> 5;
    if (lane == 0) { sh[wid] = mn; sh[4 + wid] = mx; }
    __syncthreads();
    if (threadIdx.x == 0) {
        float a = sh[0], b2 = sh[4];
        #pragma unroll
        for (int k = 1; k < 4; k++) { a = fminf(a, sh[k]); b2 = fmaxf(b2, sh[4 + k]); }
        atomicMinF(&g_red[17], a);
        atomicMaxF(&g_red[22], b2);
    }
}

// ---------------- apply scale_diff + coef mix -> g_o65 (float4, grid 1040) ----------------
__global__ void k_apply65(const float* __restrict__ coef) {
    int i4 = blockIdx.x * 256 + threadIdx.x;
    int i  = i4 << 2;
    int bc = i >> 11;
    int c = bc % 65, b = bc / 65;
    int hw = i & 2047;
    int F = c / 13, v = c % 13;
    int fi = ((b * 13 + v) << 11) + hw;
    const float* dsrc = F == 0 ? g_dzd : F == 1 ? g_dq :
                        F == 2 ? g_accu : F == 3 ? g_accv : g_acct;
    float4 base = *reinterpret_cast<const float4*>(&g_fld[F][fi]);
    float4 diff = *reinterpret_cast<const float4*>(&dsrc[fi]);
    float mn = g_red[F], mx = g_red[5 + F];
    float me = g_red[10 + F] * (1.f / 212992.f);
    float a = (mn - me) * 0.05f;
    float bb = (mx - me) * 0.05f;
    float dmn = g_red[17 + F], dmx = g_red[22 + F];
    float sc = (bb - a) / (dmx - dmn);
    float4 cf = *reinterpret_cast<const float4*>(&coef[(c << 11) + hw]);
    float4 hv = *reinterpret_cast<const float4*>(&g_h[i]);
    float4 o;
    o.x = cf.x * (base.x + (diff.x - dmn) * sc + a) + (1.f - cf.x) * hv.x;
    o.y = cf.y * (base.y + (diff.y - dmn) * sc + a) + (1.f - cf.y) * hv.y;
    o.z = cf.z * (base.z + (diff.z - dmn) * sc + a) + (1.f - cf.z) * hv.z;
    o.w = cf.w * (base.w + (diff.w - dmn) * sc + a) + (1.f - cf.w) * hv.w;
    *reinterpret_cast<float4*>(&g_o65[i]) = o;
}

// ---------------- final: BN(o2) + x (float4, grid 4096) ----------------
__global__ void k_final(const float* __restrict__ x, const float* __restrict__ gblk,
                        const float* __restrict__ bblk, float* __restrict__ out) {
    int i4 = blockIdx.x * 256 + threadIdx.x;
    int i  = i4 << 2;
    int c = (i >> 11) & 255;
    float gsc = g_is256[c] * gblk[c];
    float m = g_m256[c], bia = bblk[c];
    float4 o2 = *reinterpret_cast<const float4*>(&g_o2[i]);
    float4 xv = *reinterpret_cast<const float4*>(&x[i]);
    float4 o;
    o.x = (o2.x - m) * gsc + bia + xv.x;
    o.y = (o2.y - m) * gsc + bia + xv.y;
    o.z = (o2.z - m) * gsc + bia + xv.z;
    o.w = (o2.w - m) * gsc + bia + xv.w;
    *reinterpret_cast<float4*>(&out[i]) = o;
}

// ---------------- launcher ----------------
extern "C" void kernel_launch(void* const* d_in, const int* in_sizes, int n_in,
                              void* d_out, int out_size) {
    const float* x        = (const float*)d_in[0];
    const float* w_norm   = (const float*)d_in[1];
    const float* b_norm   = (const float*)d_in[2];
    const float* w_innorm = (const float*)d_in[3];
    const float* b_innorm = (const float*)d_in[4];
    const float* coef     = (const float*)d_in[5];
    const float* gz = (const float*)d_in[6];  const float* bz = (const float*)d_in[7];
    const float* gq = (const float*)d_in[8];  const float* bq = (const float*)d_in[9];
    const float* gu = (const float*)d_in[10]; const float* bu = (const float*)d_in[11];
    const float* gv = (const float*)d_in[12]; const float* bv = (const float*)d_in[13];
    const float* gt = (const float*)d_in[14]; const float* bt = (const float*)d_in[15];
    const float* gblk = (const float*)d_in[16];
    const float* bblk = (const float*)d_in[17];
    float* out = (float*)d_out;

    const int GF = NFE / 256;      // 832

    k_init<<<1, 64>>>();
    k_conv<256, 65, 0><<<dim3(5, 8, 8), 256>>>(x, w_norm, b_norm);
    k_bnstats<65, 0><<<65, 256>>>();
    k_bnapply<<<NHE / 1024, 256>>>(gz, bz, gq, bq, gu, bu, gv, bv, gt, bt);
    k_basederiv<<<GF, 256>>>();
    k_wvel<<<128, 128>>>();
    k_qs<<<GF, 256>>>();
    k_stage<<<GF, 256>>>(0);
    for (int s = 1; s < 4; s++) {
        k_derivAll<<<GF, 256>>>();
        k_stage<<<GF, 256>>>(s);
    }
    k_zt<<<128, 128>>>();
    k_apply65<<<NHE / 1024, 256>>>(coef);
    k_conv<65, 256, 1><<<dim3(16, 8, 8), 256>>>(nullptr, w_innorm, b_innorm);
    k_bnstats<256, 1><<<256, 256>>>();
    k_final<<<NOE / 1024, 256>>>(x, gblk, bblk, out);
}

// round 6
// speedup vs baseline: 1.4298x; 1.3596x over previous
#include <cuda_runtime.h>
#include <math.h>

// ---------------- dims ----------------
#define NFE 212992              // 8*13*32*64
#define NHE 1064960             // 8*65*32*64
#define NOE 4194304             // 8*256*32*64

// ---------------- physics consts ----------------
#define DTs    300.0f
#define KHc    15.0f
#define KVc    0.1f
#define LVc    2.5e6f
#define CPc    1005.0f
#define RGASc  8.314f
#define RDc    287.0f
#define OMEGAc 7.29e-5f
#define EMISc  0.7f
#define SIGMAc 5.67e-8f
#define PIXYc  ((float)(M_PI * 6371000.0 / 33.0))

__constant__ float c_DZ[13]  = {50.f,50.f,50.f,50.f,50.f,75.f,100.f,100.f,100.f,125.f,112.f,75.f,75.f};
__constant__ float c_PRS[13] = {50.f,100.f,150.f,200.f,250.f,300.f,400.f,500.f,600.f,700.f,850.f,925.f,1000.f};

// ---------------- scratch ----------------
__device__ float g_h[NHE], g_o65[NHE];
__device__ float g_o2[NOE];
__device__ float g_fld[5][NFE];                        // z,q,u,v,t post-BN
__device__ float g_zx[NFE], g_zy[NFE], g_zz[NFE], g_ux[NFE], g_vy[NFE];
__device__ float g_w[NFE], g_rate[NFE];
__device__ float g_sua[NFE], g_sva[NFE], g_sta[NFE];   // RK stage fields u,v,t
__device__ float g_ax[NFE], g_ay[NFE], g_az[NFE];      // u-stage derivs
__device__ float g_bx[NFE], g_by[NFE], g_bz[NFE];      // v-stage derivs
__device__ float g_cx[NFE], g_cy[NFE], g_cz[NFE];      // t-stage derivs
__device__ float g_qx[NFE], g_qy[NFE], g_qz[NFE];      // base q derivs
__device__ float g_accu[NFE], g_accv[NFE], g_acct[NFE];
__device__ float g_k4t[NFE], g_dq[NFE], g_dzd[NFE];
__device__ float g_m65[65], g_is65[65], g_m256[256], g_is256[256];
__device__ float g_red[27];
__device__ float g_invpx[32], g_fcor[32];

// red slots: 0..4 field min (z,q,u,v,t); 5..9 field max; 10..14 field sum;
//            15 sarg min; 16 sarg max; 17..21 diff min (z,q,u,v,t); 22..26 diff max

// ---------------- helpers ----------------
__device__ __forceinline__ void atomicMinF(float* a, float v) {
    if (v >= 0.f) atomicMin((int*)a, __float_as_int(v));
    else          atomicMax((unsigned int*)a, __float_as_uint(v));
}
__device__ __forceinline__ void atomicMaxF(float* a, float v) {
    if (v >= 0.f) atomicMax((int*)a, __float_as_int(v));
    else          atomicMin((unsigned int*)a, __float_as_uint(v));
}
__device__ __forceinline__ float avoid_inf1(float t) {
    if (t == 0.f) return 1.f;
    if (fabsf(t) < 1.f) return t > 0.f ? 1.f : -1.f;
    return t;
}

typedef unsigned long long u64;
__device__ __forceinline__ u64 pk2(float lo, float hi) {
    u64 r; asm("mov.b64 %0,{%1,%2};" : "=l"(r) : "f"(lo), "f"(hi)); return r;
}
__device__ __forceinline__ void fm2(u64& d, u64 a, u64 b) {
    asm("fma.rn.f32x2 %0,%1,%2,%0;" : "+l"(d) : "l"(a), "l"(b));
}
__device__ __forceinline__ void upk2(float& lo, float& hi, u64 v) {
    asm("mov.b64 {%0,%1},%2;" : "=f"(lo), "=f"(hi) : "l"(v));
}
// (hi(a), lo(b)) — the "odd" pair straddling two even pairs
__device__ __forceinline__ u64 oddpair(u64 a, u64 b) {
    u64 r;
    asm("{\n\t.reg .f32 al, ah, bl, bh;\n\t"
        "mov.b64 {al,ah}, %1;\n\t"
        "mov.b64 {bl,bh}, %2;\n\t"
        "mov.b64 %0, {ah,bl};\n\t}"
        : "=l"(r) : "l"(a), "l"(b));
    return r;
}

struct Pos { int b, v, h, w, i; };
__device__ __forceinline__ Pos decodeP(int i) {
    Pos p; p.i = i; p.w = i & 63; p.h = (i >> 6) & 31;
    int bv = i >> 11; p.v = bv % 13; p.b = bv / 13;
    return p;
}
__device__ __forceinline__ int pidxN(int m, int n) {   // block-replicate pad index
    return m < 2 ? m : (m < n + 2 ? m - 2 : m - 4);
}
__device__ __forceinline__ float dxf(const float* __restrict__ f, const Pos& p) {
    int base = p.i - p.w;
    float g = (f[base + ((p.w + 62) & 63)] - 8.f * f[base + ((p.w + 63) & 63)]
             + 8.f * f[base + ((p.w + 1) & 63)] - f[base + ((p.w + 2) & 63)]) * (1.f / 12.f);
    return g * g_invpx[p.h];
}
__device__ __forceinline__ float dyf(const float* __restrict__ f, const Pos& p) {
    int base = p.i - (p.h << 6);
    float g = (-f[base + (pidxN(p.h, 32) << 6)] + 8.f * f[base + (pidxN(p.h + 1, 32) << 6)]
             - 8.f * f[base + (pidxN(p.h + 3, 32) << 6)] + f[base + (pidxN(p.h + 4, 32) << 6)]) * (1.f / 12.f);
    return g * (1.f / PIXYc);
}
__device__ __forceinline__ float dzf(const float* __restrict__ f, const Pos& p) {
    int base = p.i - (p.v << 11);
    float g = (-f[base + (pidxN(p.v, 13) << 11)] + 8.f * f[base + (pidxN(p.v + 1, 13) << 11)]
             - 8.f * f[base + (pidxN(p.v + 3, 13) << 11)] + f[base + (pidxN(p.v + 4, 13) << 11)]) * (1.f / 12.f);
    return g / c_DZ[p.v];
}

// block reduction (blockDim == 256) -> atomics to g_red; ssum<0 skips sum
__device__ __forceinline__ void blockRed(float vmn, float vmx, float vsum,
                                         int smn, int smx, int ssum) {
    __shared__ float sh[24];
    __syncthreads();
    #pragma unroll
    for (int o = 16; o; o >>= 1) {
        vmn  = fminf(vmn, __shfl_xor_sync(0xffffffffu, vmn, o));
        vmx  = fmaxf(vmx, __shfl_xor_sync(0xffffffffu, vmx, o));
        vsum += __shfl_xor_sync(0xffffffffu, vsum, o);
    }
    int lane = threadIdx.x & 31, wid = threadIdx.x >> 5;
    if (lane == 0) { sh[wid] = vmn; sh[8 + wid] = vmx; sh[16 + wid] = vsum; }
    __syncthreads();
    if (threadIdx.x == 0) {
        float a = sh[0], b = sh[8], s = sh[16];
        #pragma unroll
        for (int k = 1; k < 8; k++) { a = fminf(a, sh[k]); b = fmaxf(b, sh[8 + k]); s += sh[16 + k]; }
        atomicMinF(&g_red[smn], a);
        atomicMaxF(&g_red[smx], b);
        if (ssum >= 0) atomicAdd(&g_red[ssum], s);
    }
}

// min/max-only block reduction for 3 pairs in one pass
__device__ __forceinline__ void blockRed3(float mn0, float mx0, float mn1, float mx1,
                                          float mn2, float mx2, int s0, int s1, int s2) {
    __shared__ float sh[48];
    __syncthreads();
    #pragma unroll
    for (int o = 16; o; o >>= 1) {
        mn0 = fminf(mn0, __shfl_xor_sync(0xffffffffu, mn0, o));
        mx0 = fmaxf(mx0, __shfl_xor_sync(0xffffffffu, mx0, o));
        mn1 = fminf(mn1, __shfl_xor_sync(0xffffffffu, mn1, o));
        mx1 = fmaxf(mx1, __shfl_xor_sync(0xffffffffu, mx1, o));
        mn2 = fminf(mn2, __shfl_xor_sync(0xffffffffu, mn2, o));
        mx2 = fmaxf(mx2, __shfl_xor_sync(0xffffffffu, mx2, o));
    }
    int lane = threadIdx.x & 31, wid = threadIdx.x >> 5;
    if (lane == 0) {
        sh[wid] = mn0; sh[8 + wid] = mx0; sh[16 + wid] = mn1;
        sh[24 + wid] = mx1; sh[32 + wid] = mn2; sh[40 + wid] = mx2;
    }
    __syncthreads();
    if (threadIdx.x == 0) {
        float a0 = sh[0], b0 = sh[8], a1 = sh[16], b1 = sh[24], a2 = sh[32], b2 = sh[40];
        #pragma unroll
        for (int k = 1; k < 8; k++) {
            a0 = fminf(a0, sh[k]);      b0 = fmaxf(b0, sh[8 + k]);
            a1 = fminf(a1, sh[16 + k]); b1 = fmaxf(b1, sh[24 + k]);
            a2 = fminf(a2, sh[32 + k]); b2 = fmaxf(b2, sh[40 + k]);
        }
        atomicMinF(&g_red[s0], a0); atomicMaxF(&g_red[s0 + 5], b0);
        atomicMinF(&g_red[s1], a1); atomicMaxF(&g_red[s1 + 5], b1);
        atomicMinF(&g_red[s2], a2); atomicMaxF(&g_red[s2 + 5], b2);
    }
}

// ---------------- init ----------------
__global__ void k_init() {
    int t = threadIdx.x;
    if (t < 32) {
        double lat = (90.0 - (double)(t + 1) * (180.0 / 33.0)) * M_PI / 180.0;
        float px = (float)(2.0 * M_PI * 6371000.0 * cos(lat) / 64.0);
        g_invpx[t] = 1.f / px;
        g_fcor[t]  = 2.0f * OMEGAc * sinf((float)lat);
    }
    if (t < 27) {
        float inf = __int_as_float(0x7f800000);
        float v;
        if (t < 5) v = inf;
        else if (t < 10) v = -inf;
        else if (t < 15) v = 0.f;
        else if (t == 15) v = inf;
        else if (t == 16) v = -inf;
        else if (t < 22) v = inf;
        else v = -inf;
        g_red[t] = v;
    }
}

// ============ conv3x3, register-tiled FFMA2 + cp.async pipeline ============
// Block: 64 threads. thread: s=tid&3 (16w), h=(tid>>2)&7 (row), g=tid>>5 (co 4-group).
// Block covers co_tile=8, h_tile=8, w=64, one b. Grid (ceil(CO/8), 4, 8).
template <int CI, int CO, int WHICH>
__global__ void __launch_bounds__(64) k_conv(const float* __restrict__ xin,
                                             const float* __restrict__ wt,
                                             const float* __restrict__ bias) {
    __shared__ __align__(16) float  xs[2][8][10][68];
    __shared__ __align__(16) float2 ws[8][9][8];
    const float* __restrict__ src = (WHICH == 0) ? xin : (const float*)g_o65;
    float* dst = (WHICH == 0) ? g_h : g_o2;

    const int tid = threadIdx.x;
    const int s = tid & 3, h = (tid >> 2) & 7, g = tid >> 5;
    const int y0 = blockIdx.y * 8, b = blockIdx.z, co0 = blockIdx.x * 8;
    const int NCH = (CI + 7) / 8;

    // zero pad columns (idx 0 and 65) in both buffers — cp.async never writes them
    for (int l = tid; l < 2 * 8 * 10; l += 64) {
        int bu = l / 80, rem = l % 80;
        int ci = rem / 10, row = rem % 10;
        xs[bu][ci][row][0]  = 0.f;
        xs[bu][ci][row][65] = 0.f;
    }

    u64 acc[4][8];
    #pragma unroll
    for (int k = 0; k < 4; k++)
        #pragma unroll
        for (int j = 0; j < 8; j++) acc[k][j] = 0ull;

    const int cix = tid & 7;        // this thread's ci for x prefetch
    const int wv0 = tid >> 3;       // w base 0..7, stride 8
    float wreg[9];

    // ---- weight gather into registers for chunk at c0 ----
    #define W_LOAD(c0)                                                        \
        _Pragma("unroll")                                                     \
        for (int m = 0; m < 9; m++) {                                         \
            int l = tid + 64 * m;                                             \
            int col = l & 7, rest = l >> 3;                                   \
            int tap = rest % 9, ci = rest / 9;                                \
            bool ok = (co0 + col) < CO && ((c0) + ci) < CI;                   \
            wreg[m] = ok ? wt[((co0 + col) * CI + (c0) + ci) * 9 + tap] : 0.f;\
        }
    // ---- duplicate weights into smem ----
    #define W_STS()                                                           \
        _Pragma("unroll")                                                     \
        for (int m = 0; m < 9; m++) {                                         \
            int l = tid + 64 * m;                                             \
            int col = l & 7, rest = l >> 3;                                   \
            int tap = rest % 9, ci = rest / 9;                                \
            ws[ci][tap][col] = make_float2(wreg[m], wreg[m]);                 \
        }
    // ---- async x tile prefetch (zero-fill via src-size=0) ----
    #define X_PREF(bu, c0)                                                    \
        {                                                                     \
            bool civ = ((c0) + cix) < CI;                                     \
            const float* sb = src + (((size_t)(b * CI + (c0) + cix)) << 11);  \
            _Pragma("unroll")                                                 \
            for (int row = 0; row < 10; row++) {                              \
                int hg = y0 - 1 + row;                                        \
                int ok = (civ && hg >= 0 && hg < 32) ? 4 : 0;                 \
                int hgc = hg < 0 ? 0 : (hg > 31 ? 31 : hg);                   \
                const float* sp = sb + hgc * 64 + wv0;                        \
                unsigned dp = (unsigned)__cvta_generic_to_shared(             \
                                  &xs[bu][cix][row][1 + wv0]);                \
                _Pragma("unroll")                                             \
                for (int jj = 0; jj < 8; jj++)                                \
                    asm volatile("cp.async.ca.shared.global [%0], [%1], 4, %2;" \
                                 :: "r"(dp + jj * 32), "l"(sp + jj * 8), "r"(ok)); \
            }                                                                 \
        }

    W_LOAD(0);
    X_PREF(0, 0);
    asm volatile("cp.async.commit_group;");

    int buf = 0;
    for (int c = 0; c < NCH; c++) {
        asm volatile("cp.async.wait_group 0;");
        __syncthreads();
        W_STS();
        if (c + 1 < NCH) { W_LOAD((c + 1) * 8); }
        __syncthreads();
        if (c + 1 < NCH) {
            X_PREF(buf ^ 1, (c + 1) * 8);
            asm volatile("cp.async.commit_group;");
        }
        // ---- compute on xs[buf] ----
        for (int ci = 0; ci < 8; ci++) {
            #pragma unroll
            for (int r = 0; r < 3; r++) {
                const float* xr = &xs[buf][ci][h + r][16 * s];
                ulonglong2 q0 = *reinterpret_cast<const ulonglong2*>(xr);
                ulonglong2 q1 = *reinterpret_cast<const ulonglong2*>(xr + 4);
                ulonglong2 q2 = *reinterpret_cast<const ulonglong2*>(xr + 8);
                ulonglong2 q3 = *reinterpret_cast<const ulonglong2*>(xr + 12);
                u64 e8 = *reinterpret_cast<const u64*>(xr + 16);
                u64 E[9] = {q0.x, q0.y, q1.x, q1.y, q2.x, q2.y, q3.x, q3.y, e8};
                u64 O[8];
                #pragma unroll
                for (int j = 0; j < 8; j++) O[j] = oddpair(E[j], E[j + 1]);
                ulonglong2 wA  = *reinterpret_cast<const ulonglong2*>(&ws[ci][r * 3 + 0][g * 4]);
                ulonglong2 wA2 = *reinterpret_cast<const ulonglong2*>(&ws[ci][r * 3 + 0][g * 4 + 2]);
                ulonglong2 wB  = *reinterpret_cast<const ulonglong2*>(&ws[ci][r * 3 + 1][g * 4]);
                ulonglong2 wB2 = *reinterpret_cast<const ulonglong2*>(&ws[ci][r * 3 + 1][g * 4 + 2]);
                ulonglong2 wC  = *reinterpret_cast<const ulonglong2*>(&ws[ci][r * 3 + 2][g * 4]);
                ulonglong2 wC2 = *reinterpret_cast<const ulonglong2*>(&ws[ci][r * 3 + 2][g * 4 + 2]);
                #pragma unroll
                for (int j = 0; j < 8; j++) {
                    fm2(acc[0][j], E[j], wA.x);  fm2(acc[0][j], O[j], wB.x);  fm2(acc[0][j], E[j + 1], wC.x);
                    fm2(acc[1][j], E[j], wA.y);  fm2(acc[1][j], O[j], wB.y);  fm2(acc[1][j], E[j + 1], wC.y);
                    fm2(acc[2][j], E[j], wA2.x); fm2(acc[2][j], O[j], wB2.x); fm2(acc[2][j], E[j + 1], wC2.x);
                    fm2(acc[3][j], E[j], wA2.y); fm2(acc[3][j], O[j], wB2.y); fm2(acc[3][j], E[j + 1], wC2.y);
                }
            }
        }
        buf ^= 1;
    }
    #undef W_LOAD
    #undef W_STS
    #undef X_PREF

    // ---- epilogue: bias + store ----
    #pragma unroll
    for (int k = 0; k < 4; k++) {
        int co = co0 + g * 4 + k;
        if (co < CO) {
            float bs = bias[co];
            float* dp = &dst[(((b * CO + co) << 5) + (y0 + h)) * 64 + 16 * s];
            #pragma unroll
            for (int m = 0; m < 4; m++) {
                float a0, a1, b0, b1;
                upk2(a0, a1, acc[k][2 * m]);
                upk2(b0, b1, acc[k][2 * m + 1]);
                float4 o = make_float4(a0 + bs, a1 + bs, b0 + bs, b1 + bs);
                *reinterpret_cast<float4*>(dp + 4 * m) = o;
            }
        }
    }
}

// ---------------- BN stats (block per channel) ----------------
template <int C, int WHICH>
__global__ void k_bnstats() {
    const float* src = (WHICH == 0) ? g_h : g_o2;
    int c = blockIdx.x;
    float s = 0.f, s2 = 0.f;
    for (int e = threadIdx.x; e < 4096; e += 256) {
        int b = e >> 9, j = (e & 511) << 2;
        float4 v4 = *reinterpret_cast<const float4*>(&src[((b * C + c) << 11) + j]);
        s  += v4.x + v4.y + v4.z + v4.w;
        s2 += v4.x * v4.x + v4.y * v4.y + v4.z * v4.z + v4.w * v4.w;
    }
    __shared__ float sh[16];
    #pragma unroll
    for (int o = 16; o; o >>= 1) {
        s  += __shfl_xor_sync(0xffffffffu, s, o);
        s2 += __shfl_xor_sync(0xffffffffu, s2, o);
    }
    int lane = threadIdx.x & 31, wid = threadIdx.x >> 5;
    if (lane == 0) { sh[wid] = s; sh[8 + wid] = s2; }
    __syncthreads();
    if (threadIdx.x == 0) {
        float a = sh[0], b2 = sh[8];
        #pragma unroll
        for (int k = 1; k < 8; k++) { a += sh[k]; b2 += sh[8 + k]; }
        float m = a * (1.f / 16384.f);
        float var = b2 * (1.f / 16384.f) - m * m;
        if (WHICH == 0) { g_m65[c] = m;  g_is65[c] = rsqrtf(var + 1e-5f); }
        else            { g_m256[c] = m; g_is256[c] = rsqrtf(var + 1e-5f); }
    }
}

// ---------------- BN apply + split + field min/max/sum (float4) ----------------
__global__ void k_bnapply(const float* gz, const float* bz, const float* gq, const float* bq,
                          const float* gu, const float* bu, const float* gv, const float* bv,
                          const float* gt, const float* bt) {
    int i4 = blockIdx.x * 256 + threadIdx.x;
    int i  = i4 << 2;
    int bc = i >> 11;
    int c = bc % 65, b = bc / 65;
    int hw = i & 2047;
    int F = c / 13, v = c % 13;
    const float* ga = F == 0 ? gz : F == 1 ? gq : F == 2 ? gu : F == 3 ? gv : gt;
    const float* be = F == 0 ? bz : F == 1 ? bq : F == 2 ? bu : F == 3 ? bv : bt;
    float gsc = g_is65[c] * ga[v];
    float m   = g_m65[c];
    float bia = be[v];
    float4 hv = *reinterpret_cast<const float4*>(&g_h[i]);
    float4 o;
    o.x = (hv.x - m) * gsc + bia; o.y = (hv.y - m) * gsc + bia;
    o.z = (hv.z - m) * gsc + bia; o.w = (hv.w - m) * gsc + bia;
    *reinterpret_cast<float4*>(&g_fld[F][((b * 13 + v) << 11) + hw]) = o;
    float mn = fminf(fminf(o.x, o.y), fminf(o.z, o.w));
    float mx = fmaxf(fmaxf(o.x, o.y), fmaxf(o.z, o.w));
    float sm = o.x + o.y + o.z + o.w;
    blockRed(mn, mx, sm, F, 5 + F, 10 + F);
}

// ---------------- base derivs (z,u,v,t,q) + sarg reduce ----------------
__global__ void k_basederiv() {
    int i = blockIdx.x * 256 + threadIdx.x;
    Pos p = decodeP(i);
    g_zx[i] = dxf(g_fld[0], p);
    g_zy[i] = dyf(g_fld[0], p);
    g_zz[i] = dzf(g_fld[0], p);
    float ux = dxf(g_fld[2], p);
    float vy = dyf(g_fld[3], p);
    g_ax[i] = ux;  g_ux[i] = ux;
    g_ay[i] = dyf(g_fld[2], p);
    g_az[i] = dzf(g_fld[2], p);
    g_bx[i] = dxf(g_fld[3], p);
    g_by[i] = vy;  g_vy[i] = vy;
    g_bz[i] = dzf(g_fld[3], p);
    g_cx[i] = dxf(g_fld[4], p);
    g_cy[i] = dyf(g_fld[4], p);
    g_cz[i] = dzf(g_fld[4], p);
    g_qx[i] = dxf(g_fld[1], p);
    g_qy[i] = dyf(g_fld[1], p);
    g_qz[i] = dzf(g_fld[1], p);
    float tc = g_fld[4][i] - 273.15f;
    float s = 17.67f * tc / avoid_inf1(tc + 243.5f);
    blockRed(s, s, 0.f, 15, 16, -1);
}

// ---------------- w_vel column integral ----------------
__global__ void k_wvel() {
    int j = blockIdx.x * 128 + threadIdx.x;       // 16384 columns
    int b = j >> 11, hw = j & 2047;
    float s = 0.f;
    for (int v = 0; v < 13; v++) {
        int off = ((b * 13 + v) << 11) + hw;
        s += c_DZ[v] * (g_ux[off] + g_vy[off]);
        g_w[off] = -s;
    }
}

// ---------------- saturation + precip rate ----------------
__global__ void k_qs() {
    int i = blockIdx.x * 256 + threadIdx.x;
    float zz = g_zz[i];
    float tt = g_fld[4][i];
    float q  = g_fld[1][i];
    float rho = -1.f / avoid_inf1(zz);
    float pr  = rho * RGASc * tt;
    float tc  = tt - 273.15f;
    float s   = 17.67f * tc / avoid_inf1(tc + 243.5f);
    float smn = g_red[15], smx = g_red[16];
    float sc  = (s - smn) / (smx - smn) * 6.48f - 3.47f;
    float es  = 6.112f * expf(sc) * 100.f;
    float qs  = fmaxf(0.622f * es / avoid_inf1(pr - 0.378f * es), 1e-6f);
    float rh  = q / avoid_inf1(qs);
    g_rate[i] = (rh > 0.8f) ? (q - 0.8f * qs) * (1.f / DTs) : 0.f;
}

// ---------------- derivatives of stage fields u,v,t ----------------
__global__ void k_derivAll() {
    int i = blockIdx.x * 256 + threadIdx.x;
    Pos p = decodeP(i);
    g_ax[i] = dxf(g_sua, p); g_ay[i] = dyf(g_sua, p); g_az[i] = dzf(g_sua, p);
    g_bx[i] = dxf(g_sva, p); g_by[i] = dyf(g_sva, p); g_bz[i] = dzf(g_sva, p);
    g_cx[i] = dxf(g_sta, p); g_cy[i] = dyf(g_sta, p); g_cz[i] = dzf(g_sta, p);
}

// ---------------- combined RK stage for u,v,t (+q tendency at stage 0) ----------------
__global__ void k_stage(int stage) {
    int i = blockIdx.x * 256 + threadIdx.x;
    Pos p = decodeP(i);
    float w  = g_w[i];
    float zz = g_zz[i];
    float f  = g_fcor[p.h];
    float u0 = g_fld[2][i], v0 = g_fld[3][i], t0 = g_fld[4][i];
    float uai = stage == 0 ? u0 : g_sua[i];
    float vai = stage == 0 ? v0 : g_sva[i];
    float tai = stage == 0 ? t0 : g_sta[i];

    float dxx_u = dxf(g_ax, p), dyy_u = dyf(g_ay, p), dzz_u = dzf(g_az, p);
    float dxx_v = dxf(g_bx, p), dyy_v = dyf(g_by, p), dzz_v = dzf(g_bz, p);
    float dxx_t = dxf(g_cx, p), dyy_t = dyf(g_cy, p), dzz_t = dzf(g_cz, p);

    float ku = -uai * g_ux[i] - vai * g_ay[i] - w * g_az[i] + f * vai - g_zx[i]
             + KHc * (dxx_u + dyy_u) + KVc * dzz_u;
    float kv = -uai * g_bx[i] - vai * g_vy[i] - w * g_bz[i] - f * uai - g_zy[i]
             + KHc * (dxx_v + dyy_v) + KVc * dzz_v;

    float taabs = tai + 273.15f;
    float t2 = taabs * taabs;
    float t5 = t2 * t2 * taabs;
    float rc = -(EMISc * SIGMAc * RDc / (CPc * 100.f)) * t5 / c_PRS[p.v];
    float lh = g_rate[i] * (LVc / CPc);
    float kt = -((LVc + 1.f) / CPc) * zz * w - u0 * g_cx[i] - v0 * g_cy[i] - w * g_cz[i]
             + KHc * (dxx_t + dyy_t) + KVc * dzz_t + rc + lh;

    if (stage == 0) {
        g_accu[i] = ku; g_accv[i] = kv; g_acct[i] = kt;
        g_sua[i] = u0 + 0.5f * DTs * ku;
        g_sva[i] = v0 + 0.5f * DTs * kv;
        g_sta[i] = t0 + 0.5f * DTs * kt;
        float dxx_q = dxf(g_qx, p), dyy_q = dyf(g_qy, p), dzz_q = dzf(g_qz, p);
        float qt = -u0 * g_qx[i] - v0 * g_qy[i] - w * g_qz[i]
                 + KHc * (dxx_q + dyy_q) + KVc * dzz_q - g_rate[i];
        float dq = qt * DTs;
        g_dq[i] = dq;
        blockRed(dq, dq, 0.f, 18, 23, -1);
    } else if (stage == 1) {
        g_accu[i] += 2.f * ku; g_accv[i] += 2.f * kv; g_acct[i] += 2.f * kt;
        g_sua[i] = u0 + 0.5f * DTs * ku;
        g_sva[i] = v0 + 0.5f * DTs * kv;
        g_sta[i] = t0 + 0.5f * DTs * kt;
    } else if (stage == 2) {
        g_accu[i] += 2.f * ku; g_accv[i] += 2.f * kv; g_acct[i] += 2.f * kt;
        g_sua[i] = u0 + DTs * ku;
        g_sva[i] = v0 + DTs * kv;
        g_sta[i] = t0 + DTs * kt;
    } else {
        g_k4t[i] = kt;
        float du = (g_accu[i] + ku) * (DTs / 6.f);
        float dv = (g_accv[i] + kv) * (DTs / 6.f);
        float dt_ = (g_acct[i] + kt) * (DTs / 6.f);
        g_accu[i] = du; g_accv[i] = dv; g_acct[i] = dt_;
        blockRed3(du, du, dv, dv, dt_, dt_, 19, 20, 21);
    }
}

// ---------------- z tendency column integral ----------------
__global__ void k_zt() {
    int j = blockIdx.x * 128 + threadIdx.x;       // 16384 columns
    int b = j >> 11, hw = j & 2047;
    float s = 0.f;
    float inf = __int_as_float(0x7f800000);
    float mn = inf, mx = -inf;
    for (int v = 0; v < 13; v++) {
        int off = ((b * 13 + v) << 11) + hw;
        s += c_DZ[v] * (-RGASc / c_PRS[v]) * g_k4t[off];
        float d = s * DTs;
        g_dzd[off] = d;
        mn = fminf(mn, d); mx = fmaxf(mx, d);
    }
    __shared__ float sh[8];
    #pragma unroll
    for (int o = 16; o; o >>= 1) {
        mn = fminf(mn, __shfl_xor_sync(0xffffffffu, mn, o));
        mx = fmaxf(mx, __shfl_xor_sync(0xffffffffu, mx, o));
    }
    int lane = threadIdx.x & 31, wid = threadIdx.x >> 5;
    if (lane == 0) { sh[wid] = mn; sh[4 + wid] = mx; }
    __syncthreads();
    if (threadIdx.x == 0) {
        float a = sh[0], b2 = sh[4];
        #pragma unroll
        for (int k = 1; k < 4; k++) { a = fminf(a, sh[k]); b2 = fmaxf(b2, sh[4 + k]); }
        atomicMinF(&g_red[17], a);
        atomicMaxF(&g_red[22], b2);
    }
}

// ---------------- apply scale_diff + coef mix -> g_o65 (float4) ----------------
__global__ void k_apply65(const float* __restrict__ coef) {
    int i4 = blockIdx.x * 256 + threadIdx.x;
    int i  = i4 << 2;
    int bc = i >> 11;
    int c = bc % 65, b = bc / 65;
    int hw = i & 2047;
    int F = c / 13, v = c % 13;
    int fi = ((b * 13 + v) << 11) + hw;
    const float* dsrc = F == 0 ? g_dzd : F == 1 ? g_dq :
                        F == 2 ? g_accu : F == 3 ? g_accv : g_acct;
    float4 base = *reinterpret_cast<const float4*>(&g_fld[F][fi]);
    float4 diff = *reinterpret_cast<const float4*>(&dsrc[fi]);
    float mn = g_red[F], mx = g_red[5 + F];
    float me = g_red[10 + F] * (1.f / 212992.f);
    float a = (mn - me) * 0.05f;
    float bb = (mx - me) * 0.05f;
    float dmn = g_red[17 + F], dmx = g_red[22 + F];
    float sc = (bb - a) / (dmx - dmn);
    float4 cf = *reinterpret_cast<const float4*>(&coef[(c << 11) + hw]);
    float4 hv = *reinterpret_cast<const float4*>(&g_h[i]);
    float4 o;
    o.x = cf.x * (base.x + (diff.x - dmn) * sc + a) + (1.f - cf.x) * hv.x;
    o.y = cf.y * (base.y + (diff.y - dmn) * sc + a) + (1.f - cf.y) * hv.y;
    o.z = cf.z * (base.z + (diff.z - dmn) * sc + a) + (1.f - cf.z) * hv.z;
    o.w = cf.w * (base.w + (diff.w - dmn) * sc + a) + (1.f - cf.w) * hv.w;
    *reinterpret_cast<float4*>(&g_o65[i]) = o;
}

// ---------------- final: BN(o2) + x (float4) ----------------
__global__ void k_final(const float* __restrict__ x, const float* __restrict__ gblk,
                        const float* __restrict__ bblk, float* __restrict__ out) {
    int i4 = blockIdx.x * 256 + threadIdx.x;
    int i  = i4 << 2;
    int c = (i >> 11) & 255;
    float gsc = g_is256[c] * gblk[c];
    float m = g_m256[c], bia = bblk[c];
    float4 o2 = *reinterpret_cast<const float4*>(&g_o2[i]);
    float4 xv = *reinterpret_cast<const float4*>(&x[i]);
    float4 o;
    o.x = (o2.x - m) * gsc + bia + xv.x;
    o.y = (o2.y - m) * gsc + bia + xv.y;
    o.z = (o2.z - m) * gsc + bia + xv.z;
    o.w = (o2.w - m) * gsc + bia + xv.w;
    *reinterpret_cast<float4*>(&out[i]) = o;
}

// ---------------- launcher ----------------
extern "C" void kernel_launch(void* const* d_in, const int* in_sizes, int n_in,
                              void* d_out, int out_size) {
    const float* x        = (const float*)d_in[0];
    const float* w_norm   = (const float*)d_in[1];
    const float* b_norm   = (const float*)d_in[2];
    const float* w_innorm = (const float*)d_in[3];
    const float* b_innorm = (const float*)d_in[4];
    const float* coef     = (const float*)d_in[5];
    const float* gz = (const float*)d_in[6];  const float* bz = (const float*)d_in[7];
    const float* gq = (const float*)d_in[8];  const float* bq = (const float*)d_in[9];
    const float* gu = (const float*)d_in[10]; const float* bu = (const float*)d_in[11];
    const float* gv = (const float*)d_in[12]; const float* bv = (const float*)d_in[13];
    const float* gt = (const float*)d_in[14]; const float* bt = (const float*)d_in[15];
    const float* gblk = (const float*)d_in[16];
    const float* bblk = (const float*)d_in[17];
    float* out = (float*)d_out;

    const int GF = NFE / 256;      // 832

    k_init<<<1, 64>>>();
    k_conv<256, 65, 0><<<dim3(9, 4, 8), 64>>>(x, w_norm, b_norm);
    k_bnstats<65, 0><<<65, 256>>>();
    k_bnapply<<<NHE / 1024, 256>>>(gz, bz, gq, bq, gu, bu, gv, bv, gt, bt);
    k_basederiv<<<GF, 256>>>();
    k_wvel<<<128, 128>>>();
    k_qs<<<GF, 256>>>();
    k_stage<<<GF, 256>>>(0);
    for (int s = 1; s < 4; s++) {
        k_derivAll<<<GF, 256>>>();
        k_stage<<<GF, 256>>>(s);
    }
    k_zt<<<128, 128>>>();
    k_apply65<<<NHE / 1024, 256>>>(coef);
    k_conv<65, 256, 1><<<dim3(32, 4, 8), 64>>>(nullptr, w_innorm, b_innorm);
    k_bnstats<256, 1><<<256, 256>>>();
    k_final<<<NOE / 1024, 256>>>(x, gblk, bblk, out);
}

// round 7
// speedup vs baseline: 1.4944x; 1.0452x over previous
#include <cuda_runtime.h>
#include <math.h>

// ---------------- dims ----------------
#define NFE 212992              // 8*13*32*64
#define NHE 1064960             // 8*65*32*64
#define NOE 4194304             // 8*256*32*64
#define GF4 208                 // NFE/4/256

// ---------------- physics consts ----------------
#define DTs    300.0f
#define KHc    15.0f
#define KVc    0.1f
#define LVc    2.5e6f
#define CPc    1005.0f
#define RGASc  8.314f
#define RDc    287.0f
#define OMEGAc 7.29e-5f
#define EMISc  0.7f
#define SIGMAc 5.67e-8f
#define PIXYc  ((float)(M_PI * 6371000.0 / 33.0))

__constant__ float c_DZ[13]  = {50.f,50.f,50.f,50.f,50.f,75.f,100.f,100.f,100.f,125.f,112.f,75.f,75.f};
__constant__ float c_PRS[13] = {50.f,100.f,150.f,200.f,250.f,300.f,400.f,500.f,600.f,700.f,850.f,925.f,1000.f};

// ---------------- scratch ----------------
__device__ float g_h[NHE], g_o65[NHE];
__device__ float g_o2[NOE];
__device__ float g_fld[5][NFE];                        // z,q,u,v,t post-BN
__device__ float g_zx[NFE], g_zy[NFE], g_zz[NFE], g_ux[NFE], g_vy[NFE];
__device__ float g_w[NFE], g_rate[NFE];
__device__ float g_sua[NFE], g_sva[NFE], g_sta[NFE];   // RK stage fields u,v,t
__device__ float g_ax[NFE], g_ay[NFE], g_az[NFE];      // u derivs (base or stage)
__device__ float g_bx[NFE], g_by[NFE], g_bz[NFE];      // v derivs
__device__ float g_cx[NFE], g_cy[NFE], g_cz[NFE];      // t derivs
__device__ float g_qx[NFE], g_qy[NFE], g_qz[NFE];      // base q derivs
__device__ float g_accu[NFE], g_accv[NFE], g_acct[NFE];
__device__ float g_k4t[NFE], g_dq[NFE], g_dzd[NFE];
__device__ float g_m65[65], g_is65[65], g_m256[256], g_is256[256];
__device__ float g_red[27];
__device__ float g_invpx[32], g_fcor[32];

// red slots: 0..4 field min (z,q,u,v,t); 5..9 field max; 10..14 field sum;
//            15 sarg min; 16 sarg max; 17..21 diff min (z,q,u,v,t); 22..26 diff max

// ---------------- helpers ----------------
__device__ __forceinline__ void atomicMinF(float* a, float v) {
    if (v >= 0.f) atomicMin((int*)a, __float_as_int(v));
    else          atomicMax((unsigned int*)a, __float_as_uint(v));
}
__device__ __forceinline__ void atomicMaxF(float* a, float v) {
    if (v >= 0.f) atomicMax((int*)a, __float_as_int(v));
    else          atomicMin((unsigned int*)a, __float_as_uint(v));
}
__device__ __forceinline__ float avoid_inf1(float t) {
    if (t == 0.f) return 1.f;
    if (fabsf(t) < 1.f) return t > 0.f ? 1.f : -1.f;
    return t;
}

typedef unsigned long long u64;
__device__ __forceinline__ u64 pk2(float lo, float hi) {
    u64 r; asm("mov.b64 %0,{%1,%2};" : "=l"(r) : "f"(lo), "f"(hi)); return r;
}
__device__ __forceinline__ void fm2(u64& d, u64 a, u64 b) {
    asm("fma.rn.f32x2 %0,%1,%2,%0;" : "+l"(d) : "l"(a), "l"(b));
}
__device__ __forceinline__ void upk2(float& lo, float& hi, u64 v) {
    asm("mov.b64 {%0,%1},%2;" : "=f"(lo), "=f"(hi) : "l"(v));
}
__device__ __forceinline__ u64 oddpair(u64 a, u64 b) {
    u64 r;
    asm("{\n\t.reg .f32 al, ah, bl, bh;\n\t"
        "mov.b64 {al,ah}, %1;\n\t"
        "mov.b64 {bl,bh}, %2;\n\t"
        "mov.b64 %0, {ah,bl};\n\t}"
        : "=l"(r) : "l"(a), "l"(b));
    return r;
}

__device__ __forceinline__ int pidxN(int m, int n) {   // block-replicate pad index
    return m < 2 ? m : (m < n + 2 ? m - 2 : m - 4);
}

// ---------------- 4-wide packet (4 consecutive w) ----------------
struct P4 { int i, v, h, w0; };
__device__ __forceinline__ P4 decode4(int i4) {
    P4 p; int i = i4 << 2;
    p.i = i; p.w0 = i & 63; p.h = (i >> 6) & 31;
    p.v = (i >> 11) % 13;
    return p;
}
__device__ __forceinline__ void ld4(float* d, const float* __restrict__ f, int idx) {
    float4 t = *reinterpret_cast<const float4*>(f + idx);
    d[0] = t.x; d[1] = t.y; d[2] = t.z; d[3] = t.w;
}
__device__ __forceinline__ void st4(float* f, int idx, const float* s) {
    *reinterpret_cast<float4*>(f + idx) = make_float4(s[0], s[1], s[2], s[3]);
}
// d/dx (periodic along w)
__device__ __forceinline__ void dx4(float* out, const float* __restrict__ f,
                                    const P4& p, float invpx) {
    float win[12];
    int rb = p.i - p.w0;
    ld4(win,     f, rb + ((p.w0 + 60) & 63));
    ld4(win + 4, f, p.i);
    ld4(win + 8, f, rb + ((p.w0 + 4) & 63));
    #pragma unroll
    for (int k = 0; k < 4; k++)
        out[k] = (win[2 + k] - 8.f * win[3 + k] + 8.f * win[5 + k] - win[6 + k])
               * (1.f / 12.f) * invpx;
}
// d/dy (block-replicate pad along h)
__device__ __forceinline__ void dy4(float* out, const float* __restrict__ f, const P4& p) {
    float a[4], b[4], c[4], d[4];
    ld4(a, f, p.i + ((pidxN(p.h,     32) - p.h) << 6));
    ld4(b, f, p.i + ((pidxN(p.h + 1, 32) - p.h) << 6));
    ld4(c, f, p.i + ((pidxN(p.h + 3, 32) - p.h) << 6));
    ld4(d, f, p.i + ((pidxN(p.h + 4, 32) - p.h) << 6));
    #pragma unroll
    for (int k = 0; k < 4; k++)
        out[k] = (-a[k] + 8.f * b[k] - 8.f * c[k] + d[k]) * (1.f / 12.f) * (1.f / PIXYc);
}
// d/dz (block-replicate pad along v)
__device__ __forceinline__ void dz4(float* out, const float* __restrict__ f, const P4& p) {
    float a[4], b[4], c[4], d[4];
    ld4(a, f, p.i + ((pidxN(p.v,     13) - p.v) << 11));
    ld4(b, f, p.i + ((pidxN(p.v + 1, 13) - p.v) << 11));
    ld4(c, f, p.i + ((pidxN(p.v + 3, 13) - p.v) << 11));
    ld4(d, f, p.i + ((pidxN(p.v + 4, 13) - p.v) << 11));
    float r = 1.f / (12.f * c_DZ[p.v]);
    #pragma unroll
    for (int k = 0; k < 4; k++)
        out[k] = (-a[k] + 8.f * b[k] - 8.f * c[k] + d[k]) * r;
}

// block reduction (blockDim == 256) -> atomics to g_red; ssum<0 skips sum
__device__ __forceinline__ void blockRed(float vmn, float vmx, float vsum,
                                         int smn, int smx, int ssum) {
    __shared__ float sh[24];
    __syncthreads();
    #pragma unroll
    for (int o = 16; o; o >>= 1) {
        vmn  = fminf(vmn, __shfl_xor_sync(0xffffffffu, vmn, o));
        vmx  = fmaxf(vmx, __shfl_xor_sync(0xffffffffu, vmx, o));
        vsum += __shfl_xor_sync(0xffffffffu, vsum, o);
    }
    int lane = threadIdx.x & 31, wid = threadIdx.x >> 5;
    if (lane == 0) { sh[wid] = vmn; sh[8 + wid] = vmx; sh[16 + wid] = vsum; }
    __syncthreads();
    if (threadIdx.x == 0) {
        float a = sh[0], b = sh[8], s = sh[16];
        #pragma unroll
        for (int k = 1; k < 8; k++) { a = fminf(a, sh[k]); b = fmaxf(b, sh[8 + k]); s += sh[16 + k]; }
        atomicMinF(&g_red[smn], a);
        atomicMaxF(&g_red[smx], b);
        if (ssum >= 0) atomicAdd(&g_red[ssum], s);
    }
}

// min/max-only block reduction for 3 pairs in one pass
__device__ __forceinline__ void blockRed3(float mn0, float mx0, float mn1, float mx1,
                                          float mn2, float mx2, int s0, int s1, int s2) {
    __shared__ float sh[48];
    __syncthreads();
    #pragma unroll
    for (int o = 16; o; o >>= 1) {
        mn0 = fminf(mn0, __shfl_xor_sync(0xffffffffu, mn0, o));
        mx0 = fmaxf(mx0, __shfl_xor_sync(0xffffffffu, mx0, o));
        mn1 = fminf(mn1, __shfl_xor_sync(0xffffffffu, mn1, o));
        mx1 = fmaxf(mx1, __shfl_xor_sync(0xffffffffu, mx1, o));
        mn2 = fminf(mn2, __shfl_xor_sync(0xffffffffu, mn2, o));
        mx2 = fmaxf(mx2, __shfl_xor_sync(0xffffffffu, mx2, o));
    }
    int lane = threadIdx.x & 31, wid = threadIdx.x >> 5;
    if (lane == 0) {
        sh[wid] = mn0; sh[8 + wid] = mx0; sh[16 + wid] = mn1;
        sh[24 + wid] = mx1; sh[32 + wid] = mn2; sh[40 + wid] = mx2;
    }
    __syncthreads();
    if (threadIdx.x == 0) {
        float a0 = sh[0], b0 = sh[8], a1 = sh[16], b1 = sh[24], a2 = sh[32], b2 = sh[40];
        #pragma unroll
        for (int k = 1; k < 8; k++) {
            a0 = fminf(a0, sh[k]);      b0 = fmaxf(b0, sh[8 + k]);
            a1 = fminf(a1, sh[16 + k]); b1 = fmaxf(b1, sh[24 + k]);
            a2 = fminf(a2, sh[32 + k]); b2 = fmaxf(b2, sh[40 + k]);
        }
        atomicMinF(&g_red[s0], a0); atomicMaxF(&g_red[s0 + 5], b0);
        atomicMinF(&g_red[s1], a1); atomicMaxF(&g_red[s1 + 5], b1);
        atomicMinF(&g_red[s2], a2); atomicMaxF(&g_red[s2 + 5], b2);
    }
}

// ---------------- init ----------------
__global__ void k_init() {
    int t = threadIdx.x;
    if (t < 32) {
        double lat = (90.0 - (double)(t + 1) * (180.0 / 33.0)) * M_PI / 180.0;
        float px = (float)(2.0 * M_PI * 6371000.0 * cos(lat) / 64.0);
        g_invpx[t] = 1.f / px;
        g_fcor[t]  = 2.0f * OMEGAc * sinf((float)lat);
    }
    if (t < 27) {
        float inf = __int_as_float(0x7f800000);
        float v;
        if (t < 5) v = inf;
        else if (t < 10) v = -inf;
        else if (t < 15) v = 0.f;
        else if (t == 15) v = inf;
        else if (t == 16) v = -inf;
        else if (t < 22) v = inf;
        else v = -inf;
        g_red[t] = v;
    }
}

// ============ conv3x3, register-tiled FFMA2 + cp.async pipeline ============
template <int CI, int CO, int WHICH>
__global__ void __launch_bounds__(64) k_conv(const float* __restrict__ xin,
                                             const float* __restrict__ wt,
                                             const float* __restrict__ bias) {
    __shared__ __align__(16) float  xs[2][8][10][68];
    __shared__ __align__(16) float2 ws[8][9][8];
    const float* __restrict__ src = (WHICH == 0) ? xin : (const float*)g_o65;
    float* dst = (WHICH == 0) ? g_h : g_o2;

    const int tid = threadIdx.x;
    const int s = tid & 3, h = (tid >> 2) & 7, g = tid >> 5;
    const int y0 = blockIdx.y * 8, b = blockIdx.z, co0 = blockIdx.x * 8;
    const int NCH = (CI + 7) / 8;

    for (int l = tid; l < 2 * 8 * 10; l += 64) {
        int bu = l / 80, rem = l % 80;
        int ci = rem / 10, row = rem % 10;
        xs[bu][ci][row][0]  = 0.f;
        xs[bu][ci][row][65] = 0.f;
    }

    u64 acc[4][8];
    #pragma unroll
    for (int k = 0; k < 4; k++)
        #pragma unroll
        for (int j = 0; j < 8; j++) acc[k][j] = 0ull;

    const int cix = tid & 7;
    const int wv0 = tid >> 3;
    float wreg[9];

    #define W_LOAD(c0)                                                        \
        _Pragma("unroll")                                                     \
        for (int m = 0; m < 9; m++) {                                         \
            int l = tid + 64 * m;                                             \
            int col = l & 7, rest = l >> 3;                                   \
            int tap = rest % 9, ci = rest / 9;                                \
            bool ok = (co0 + col) < CO && ((c0) + ci) < CI;                   \
            wreg[m] = ok ? wt[((co0 + col) * CI + (c0) + ci) * 9 + tap] : 0.f;\
        }
    #define W_STS()                                                           \
        _Pragma("unroll")                                                     \
        for (int m = 0; m < 9; m++) {                                         \
            int l = tid + 64 * m;                                             \
            int col = l & 7, rest = l >> 3;                                   \
            int tap = rest % 9, ci = rest / 9;                                \
            ws[ci][tap][col] = make_float2(wreg[m], wreg[m]);                 \
        }
    #define X_PREF(bu, c0)                                                    \
        {                                                                     \
            bool civ = ((c0) + cix) < CI;                                     \
            const float* sb = src + (((size_t)(b * CI + (c0) + cix)) << 11);  \
            _Pragma("unroll")                                                 \
            for (int row = 0; row < 10; row++) {                              \
                int hg = y0 - 1 + row;                                        \
                int ok = (civ && hg >= 0 && hg < 32) ? 4 : 0;                 \
                int hgc = hg < 0 ? 0 : (hg > 31 ? 31 : hg);                   \
                const float* sp = sb + hgc * 64 + wv0;                        \
                unsigned dp = (unsigned)__cvta_generic_to_shared(             \
                                  &xs[bu][cix][row][1 + wv0]);                \
                _Pragma("unroll")                                             \
                for (int jj = 0; jj < 8; jj++)                                \
                    asm volatile("cp.async.ca.shared.global [%0], [%1], 4, %2;" \
                                 :: "r"(dp + jj * 32), "l"(sp + jj * 8), "r"(ok)); \
            }                                                                 \
        }

    W_LOAD(0);
    X_PREF(0, 0);
    asm volatile("cp.async.commit_group;");

    int buf = 0;
    for (int c = 0; c < NCH; c++) {
        asm volatile("cp.async.wait_group 0;");
        __syncthreads();
        W_STS();
        if (c + 1 < NCH) { W_LOAD((c + 1) * 8); }
        __syncthreads();
        if (c + 1 < NCH) {
            X_PREF(buf ^ 1, (c + 1) * 8);
            asm volatile("cp.async.commit_group;");
        }
        for (int ci = 0; ci < 8; ci++) {
            #pragma unroll
            for (int r = 0; r < 3; r++) {
                const float* xr = &xs[buf][ci][h + r][16 * s];
                ulonglong2 q0 = *reinterpret_cast<const ulonglong2*>(xr);
                ulonglong2 q1 = *reinterpret_cast<const ulonglong2*>(xr + 4);
                ulonglong2 q2 = *reinterpret_cast<const ulonglong2*>(xr + 8);
                ulonglong2 q3 = *reinterpret_cast<const ulonglong2*>(xr + 12);
                u64 e8 = *reinterpret_cast<const u64*>(xr + 16);
                u64 E[9] = {q0.x, q0.y, q1.x, q1.y, q2.x, q2.y, q3.x, q3.y, e8};
                u64 O[8];
                #pragma unroll
                for (int j = 0; j < 8; j++) O[j] = oddpair(E[j], E[j + 1]);
                ulonglong2 wA  = *reinterpret_cast<const ulonglong2*>(&ws[ci][r * 3 + 0][g * 4]);
                ulonglong2 wA2 = *reinterpret_cast<const ulonglong2*>(&ws[ci][r * 3 + 0][g * 4 + 2]);
                ulonglong2 wB  = *reinterpret_cast<const ulonglong2*>(&ws[ci][r * 3 + 1][g * 4]);
                ulonglong2 wB2 = *reinterpret_cast<const ulonglong2*>(&ws[ci][r * 3 + 1][g * 4 + 2]);
                ulonglong2 wC  = *reinterpret_cast<const ulonglong2*>(&ws[ci][r * 3 + 2][g * 4]);
                ulonglong2 wC2 = *reinterpret_cast<const ulonglong2*>(&ws[ci][r * 3 + 2][g * 4 + 2]);
                #pragma unroll
                for (int j = 0; j < 8; j++) {
                    fm2(acc[0][j], E[j], wA.x);  fm2(acc[0][j], O[j], wB.x);  fm2(acc[0][j], E[j + 1], wC.x);
                    fm2(acc[1][j], E[j], wA.y);  fm2(acc[1][j], O[j], wB.y);  fm2(acc[1][j], E[j + 1], wC.y);
                    fm2(acc[2][j], E[j], wA2.x); fm2(acc[2][j], O[j], wB2.x); fm2(acc[2][j], E[j + 1], wC2.x);
                    fm2(acc[3][j], E[j], wA2.y); fm2(acc[3][j], O[j], wB2.y); fm2(acc[3][j], E[j + 1], wC2.y);
                }
            }
        }
        buf ^= 1;
    }
    #undef W_LOAD
    #undef W_STS
    #undef X_PREF

    #pragma unroll
    for (int k = 0; k < 4; k++) {
        int co = co0 + g * 4 + k;
        if (co < CO) {
            float bs = bias[co];
            float* dp = &dst[(((b * CO + co) << 5) + (y0 + h)) * 64 + 16 * s];
            #pragma unroll
            for (int m = 0; m < 4; m++) {
                float a0, a1, b0, b1;
                upk2(a0, a1, acc[k][2 * m]);
                upk2(b0, b1, acc[k][2 * m + 1]);
                float4 o = make_float4(a0 + bs, a1 + bs, b0 + bs, b1 + bs);
                *reinterpret_cast<float4*>(dp + 4 * m) = o;
            }
        }
    }
}

// ---------------- BN stats (block per channel) ----------------
template <int C, int WHICH>
__global__ void k_bnstats() {
    const float* src = (WHICH == 0) ? g_h : g_o2;
    int c = blockIdx.x;
    float s = 0.f, s2 = 0.f;
    for (int e = threadIdx.x; e < 4096; e += 256) {
        int b = e >> 9, j = (e & 511) << 2;
        float4 v4 = *reinterpret_cast<const float4*>(&src[((b * C + c) << 11) + j]);
        s  += v4.x + v4.y + v4.z + v4.w;
        s2 += v4.x * v4.x + v4.y * v4.y + v4.z * v4.z + v4.w * v4.w;
    }
    __shared__ float sh[16];
    #pragma unroll
    for (int o = 16; o; o >>= 1) {
        s  += __shfl_xor_sync(0xffffffffu, s, o);
        s2 += __shfl_xor_sync(0xffffffffu, s2, o);
    }
    int lane = threadIdx.x & 31, wid = threadIdx.x >> 5;
    if (lane == 0) { sh[wid] = s; sh[8 + wid] = s2; }
    __syncthreads();
    if (threadIdx.x == 0) {
        float a = sh[0], b2 = sh[8];
        #pragma unroll
        for (int k = 1; k < 8; k++) { a += sh[k]; b2 += sh[8 + k]; }
        float m = a * (1.f / 16384.f);
        float var = b2 * (1.f / 16384.f) - m * m;
        if (WHICH == 0) { g_m65[c] = m;  g_is65[c] = rsqrtf(var + 1e-5f); }
        else            { g_m256[c] = m; g_is256[c] = rsqrtf(var + 1e-5f); }
    }
}

// ---------------- BN apply + split + field min/max/sum ----------------
__global__ void k_bnapply(const float* gz, const float* bz, const float* gq, const float* bq,
                          const float* gu, const float* bu, const float* gv, const float* bv,
                          const float* gt, const float* bt) {
    int i4 = blockIdx.x * 256 + threadIdx.x;
    int i  = i4 << 2;
    int bc = i >> 11;
    int c = bc % 65, b = bc / 65;
    int hw = i & 2047;
    int F = c / 13, v = c % 13;
    const float* ga = F == 0 ? gz : F == 1 ? gq : F == 2 ? gu : F == 3 ? gv : gt;
    const float* be = F == 0 ? bz : F == 1 ? bq : F == 2 ? bu : F == 3 ? bv : bt;
    float gsc = g_is65[c] * ga[v];
    float m   = g_m65[c];
    float bia = be[v];
    float4 hv = *reinterpret_cast<const float4*>(&g_h[i]);
    float4 o;
    o.x = (hv.x - m) * gsc + bia; o.y = (hv.y - m) * gsc + bia;
    o.z = (hv.z - m) * gsc + bia; o.w = (hv.w - m) * gsc + bia;
    *reinterpret_cast<float4*>(&g_fld[F][((b * 13 + v) << 11) + hw]) = o;
    float mn = fminf(fminf(o.x, o.y), fminf(o.z, o.w));
    float mx = fmaxf(fmaxf(o.x, o.y), fmaxf(o.z, o.w));
    float sm = o.x + o.y + o.z + o.w;
    blockRed(mn, mx, sm, F, 5 + F, 10 + F);
}

// ---------------- base derivs (z,u,v,t,q) + sarg reduce (4-wide) ----------------
__global__ void k_basederiv() {
    int i4 = blockIdx.x * 256 + threadIdx.x;
    P4 p = decode4(i4);
    float invpx = g_invpx[p.h];
    float t1[4];
    dx4(t1, g_fld[0], p, invpx); st4(g_zx, p.i, t1);
    dy4(t1, g_fld[0], p);        st4(g_zy, p.i, t1);
    dz4(t1, g_fld[0], p);        st4(g_zz, p.i, t1);
    dx4(t1, g_fld[2], p, invpx); st4(g_ux, p.i, t1); st4(g_ax, p.i, t1);
    dy4(t1, g_fld[2], p);        st4(g_ay, p.i, t1);
    dz4(t1, g_fld[2], p);        st4(g_az, p.i, t1);
    dx4(t1, g_fld[3], p, invpx); st4(g_bx, p.i, t1);
    dy4(t1, g_fld[3], p);        st4(g_vy, p.i, t1); st4(g_by, p.i, t1);
    dz4(t1, g_fld[3], p);        st4(g_bz, p.i, t1);
    dx4(t1, g_fld[4], p, invpx); st4(g_cx, p.i, t1);
    dy4(t1, g_fld[4], p);        st4(g_cy, p.i, t1);
    dz4(t1, g_fld[4], p);        st4(g_cz, p.i, t1);
    dx4(t1, g_fld[1], p, invpx); st4(g_qx, p.i, t1);
    dy4(t1, g_fld[1], p);        st4(g_qy, p.i, t1);
    dz4(t1, g_fld[1], p);        st4(g_qz, p.i, t1);
    float tt[4];
    ld4(tt, g_fld[4], p.i);
    float smn = __int_as_float(0x7f800000), smx = -smn;
    #pragma unroll
    for (int k = 0; k < 4; k++) {
        float tc = tt[k] - 273.15f;
        float s = 17.67f * tc / avoid_inf1(tc + 243.5f);
        smn = fminf(smn, s); smx = fmaxf(smx, s);
    }
    blockRed(smn, smx, 0.f, 15, 16, -1);
}

// ---------------- w_vel column integral ----------------
__global__ void k_wvel() {
    int j = blockIdx.x * 128 + threadIdx.x;       // 16384 columns
    int b = j >> 11, hw = j & 2047;
    float s = 0.f;
    for (int v = 0; v < 13; v++) {
        int off = ((b * 13 + v) << 11) + hw;
        s += c_DZ[v] * (g_ux[off] + g_vy[off]);
        g_w[off] = -s;
    }
}

// ---------------- derivatives of stage fields u,v,t (4-wide) ----------------
__global__ void k_derivAll() {
    int i4 = blockIdx.x * 256 + threadIdx.x;
    P4 p = decode4(i4);
    float invpx = g_invpx[p.h];
    float t1[4];
    dx4(t1, g_sua, p, invpx); st4(g_ax, p.i, t1);
    dy4(t1, g_sua, p);        st4(g_ay, p.i, t1);
    dz4(t1, g_sua, p);        st4(g_az, p.i, t1);
    dx4(t1, g_sva, p, invpx); st4(g_bx, p.i, t1);
    dy4(t1, g_sva, p);        st4(g_by, p.i, t1);
    dz4(t1, g_sva, p);        st4(g_bz, p.i, t1);
    dx4(t1, g_sta, p, invpx); st4(g_cx, p.i, t1);
    dy4(t1, g_sta, p);        st4(g_cy, p.i, t1);
    dz4(t1, g_sta, p);        st4(g_cz, p.i, t1);
}

// ---------------- combined RK stage (u,v,t; +qs/q-tendency at stage 0) ----------------
__global__ void k_stage(int stage) {
    int i4 = blockIdx.x * 256 + threadIdx.x;
    P4 p = decode4(i4);
    float invpx = g_invpx[p.h];
    float fco = g_fcor[p.h];

    float w_[4], zz[4], u0[4], v0[4], t0[4];
    ld4(w_, g_w, p.i); ld4(zz, g_zz, p.i);
    ld4(u0, g_fld[2], p.i); ld4(v0, g_fld[3], p.i); ld4(t0, g_fld[4], p.i);

    float ua[4], va[4], ta[4];
    if (stage == 0) {
        #pragma unroll
        for (int k = 0; k < 4; k++) { ua[k] = u0[k]; va[k] = v0[k]; ta[k] = t0[k]; }
    } else {
        ld4(ua, g_sua, p.i); ld4(va, g_sva, p.i); ld4(ta, g_sta, p.i);
    }

    float rate[4];
    if (stage == 0) {
        // fused saturation + precip rate
        float q_[4]; ld4(q_, g_fld[1], p.i);
        float smn = g_red[15], smx = g_red[16];
        float rcp = 6.48f / (smx - smn);
        #pragma unroll
        for (int k = 0; k < 4; k++) {
            float rho = -1.f / avoid_inf1(zz[k]);
            float pr  = rho * RGASc * t0[k];
            float tc  = t0[k] - 273.15f;
            float s   = 17.67f * tc / avoid_inf1(tc + 243.5f);
            float sc  = (s - smn) * rcp - 3.47f;
            float es  = 6.112f * expf(sc) * 100.f;
            float qs  = fmaxf(0.622f * es / avoid_inf1(pr - 0.378f * es), 1e-6f);
            float rh  = q_[k] / avoid_inf1(qs);
            rate[k]   = (rh > 0.8f) ? (q_[k] - 0.8f * qs) * (1.f / DTs) : 0.f;
        }
        st4(g_rate, p.i, rate);
    } else {
        ld4(rate, g_rate, p.i);
    }

    float tmp[4], ku[4], kv[4], kt[4];
    // ---- ku ----
    dx4(tmp, g_ax, p, invpx);
    #pragma unroll
    for (int k = 0; k < 4; k++) ku[k] = KHc * tmp[k];
    dy4(tmp, g_ay, p);
    #pragma unroll
    for (int k = 0; k < 4; k++) ku[k] += KHc * tmp[k];
    dz4(tmp, g_az, p);
    #pragma unroll
    for (int k = 0; k < 4; k++) ku[k] += KVc * tmp[k];
    ld4(tmp, g_ux, p.i);
    #pragma unroll
    for (int k = 0; k < 4; k++) ku[k] -= ua[k] * tmp[k];
    ld4(tmp, g_ay, p.i);
    #pragma unroll
    for (int k = 0; k < 4; k++) ku[k] -= va[k] * tmp[k];
    ld4(tmp, g_az, p.i);
    #pragma unroll
    for (int k = 0; k < 4; k++) ku[k] -= w_[k] * tmp[k];
    ld4(tmp, g_zx, p.i);
    #pragma unroll
    for (int k = 0; k < 4; k++) ku[k] += fco * va[k] - tmp[k];
    // ---- kv ----
    dx4(tmp, g_bx, p, invpx);
    #pragma unroll
    for (int k = 0; k < 4; k++) kv[k] = KHc * tmp[k];
    dy4(tmp, g_by, p);
    #pragma unroll
    for (int k = 0; k < 4; k++) kv[k] += KHc * tmp[k];
    dz4(tmp, g_bz, p);
    #pragma unroll
    for (int k = 0; k < 4; k++) kv[k] += KVc * tmp[k];
    ld4(tmp, g_bx, p.i);
    #pragma unroll
    for (int k = 0; k < 4; k++) kv[k] -= ua[k] * tmp[k];
    ld4(tmp, g_vy, p.i);
    #pragma unroll
    for (int k = 0; k < 4; k++) kv[k] -= va[k] * tmp[k];
    ld4(tmp, g_bz, p.i);
    #pragma unroll
    for (int k = 0; k < 4; k++) kv[k] -= w_[k] * tmp[k];
    ld4(tmp, g_zy, p.i);
    #pragma unroll
    for (int k = 0; k < 4; k++) kv[k] += -fco * ua[k] - tmp[k];
    // ---- kt ----
    dx4(tmp, g_cx, p, invpx);
    #pragma unroll
    for (int k = 0; k < 4; k++) kt[k] = KHc * tmp[k];
    dy4(tmp, g_cy, p);
    #pragma unroll
    for (int k = 0; k < 4; k++) kt[k] += KHc * tmp[k];
    dz4(tmp, g_cz, p);
    #pragma unroll
    for (int k = 0; k < 4; k++) kt[k] += KVc * tmp[k];
    ld4(tmp, g_cx, p.i);
    #pragma unroll
    for (int k = 0; k < 4; k++) kt[k] -= u0[k] * tmp[k];
    ld4(tmp, g_cy, p.i);
    #pragma unroll
    for (int k = 0; k < 4; k++) kt[k] -= v0[k] * tmp[k];
    ld4(tmp, g_cz, p.i);
    #pragma unroll
    for (int k = 0; k < 4; k++) kt[k] -= w_[k] * tmp[k];
    float iprs = 1.f / c_PRS[p.v];
    #pragma unroll
    for (int k = 0; k < 4; k++) {
        float taabs = ta[k] + 273.15f;
        float t2 = taabs * taabs;
        float t5 = t2 * t2 * taabs;
        float rc = -(EMISc * SIGMAc * RDc / (CPc * 100.f)) * t5 * iprs;
        kt[k] += -((LVc + 1.f) / CPc) * zz[k] * w_[k] + rc + rate[k] * (LVc / CPc);
    }

    if (stage == 0) {
        st4(g_accu, p.i, ku); st4(g_accv, p.i, kv); st4(g_acct, p.i, kt);
        #pragma unroll
        for (int k = 0; k < 4; k++) {
            ku[k] = u0[k] + 0.5f * DTs * ku[k];
            kv[k] = v0[k] + 0.5f * DTs * kv[k];
            kt[k] = t0[k] + 0.5f * DTs * kt[k];
        }
        st4(g_sua, p.i, ku); st4(g_sva, p.i, kv); st4(g_sta, p.i, kt);
        // ---- q tendency (base derivs) ----
        float qt[4];
        dx4(tmp, g_qx, p, invpx);
        #pragma unroll
        for (int k = 0; k < 4; k++) qt[k] = KHc * tmp[k];
        dy4(tmp, g_qy, p);
        #pragma unroll
        for (int k = 0; k < 4; k++) qt[k] += KHc * tmp[k];
        dz4(tmp, g_qz, p);
        #pragma unroll
        for (int k = 0; k < 4; k++) qt[k] += KVc * tmp[k];
        ld4(tmp, g_qx, p.i);
        #pragma unroll
        for (int k = 0; k < 4; k++) qt[k] -= u0[k] * tmp[k];
        ld4(tmp, g_qy, p.i);
        #pragma unroll
        for (int k = 0; k < 4; k++) qt[k] -= v0[k] * tmp[k];
        ld4(tmp, g_qz, p.i);
        #pragma unroll
        for (int k = 0; k < 4; k++) qt[k] = (qt[k] - w_[k] * tmp[k] - rate[k]) * DTs;
        st4(g_dq, p.i, qt);
        float qmn = fminf(fminf(qt[0], qt[1]), fminf(qt[2], qt[3]));
        float qmx = fmaxf(fmaxf(qt[0], qt[1]), fmaxf(qt[2], qt[3]));
        blockRed(qmn, qmx, 0.f, 18, 23, -1);
    } else if (stage == 1 || stage == 2) {
        float au[4], av[4], at[4];
        ld4(au, g_accu, p.i); ld4(av, g_accv, p.i); ld4(at, g_acct, p.i);
        #pragma unroll
        for (int k = 0; k < 4; k++) { au[k] += 2.f * ku[k]; av[k] += 2.f * kv[k]; at[k] += 2.f * kt[k]; }
        st4(g_accu, p.i, au); st4(g_accv, p.i, av); st4(g_acct, p.i, at);
        float cdt = (stage == 1) ? 0.5f * DTs : DTs;
        #pragma unroll
        for (int k = 0; k < 4; k++) {
            ku[k] = u0[k] + cdt * ku[k];
            kv[k] = v0[k] + cdt * kv[k];
            kt[k] = t0[k] + cdt * kt[k];
        }
        st4(g_sua, p.i, ku); st4(g_sva, p.i, kv); st4(g_sta, p.i, kt);
    } else {
        st4(g_k4t, p.i, kt);
        float au[4], av[4], at[4];
        ld4(au, g_accu, p.i); ld4(av, g_accv, p.i); ld4(at, g_acct, p.i);
        #pragma unroll
        for (int k = 0; k < 4; k++) {
            au[k] = (au[k] + ku[k]) * (DTs / 6.f);
            av[k] = (av[k] + kv[k]) * (DTs / 6.f);
            at[k] = (at[k] + kt[k]) * (DTs / 6.f);
        }
        st4(g_accu, p.i, au); st4(g_accv, p.i, av); st4(g_acct, p.i, at);
        float umn = fminf(fminf(au[0], au[1]), fminf(au[2], au[3]));
        float umx = fmaxf(fmaxf(au[0], au[1]), fmaxf(au[2], au[3]));
        float vmn = fminf(fminf(av[0], av[1]), fminf(av[2], av[3]));
        float vmx = fmaxf(fmaxf(av[0], av[1]), fmaxf(av[2], av[3]));
        float tmn = fminf(fminf(at[0], at[1]), fminf(at[2], at[3]));
        float tmx = fmaxf(fmaxf(at[0], at[1]), fmaxf(at[2], at[3]));
        blockRed3(umn, umx, vmn, vmx, tmn, tmx, 19, 20, 21);
    }
}

// ---------------- z tendency column integral ----------------
__global__ void k_zt() {
    int j = blockIdx.x * 128 + threadIdx.x;       // 16384 columns
    int b = j >> 11, hw = j & 2047;
    float s = 0.f;
    float inf = __int_as_float(0x7f800000);
    float mn = inf, mx = -inf;
    for (int v = 0; v < 13; v++) {
        int off = ((b * 13 + v) << 11) + hw;
        s += c_DZ[v] * (-RGASc / c_PRS[v]) * g_k4t[off];
        float d = s * DTs;
        g_dzd[off] = d;
        mn = fminf(mn, d); mx = fmaxf(mx, d);
    }
    __shared__ float sh[8];
    #pragma unroll
    for (int o = 16; o; o >>= 1) {
        mn = fminf(mn, __shfl_xor_sync(0xffffffffu, mn, o));
        mx = fmaxf(mx, __shfl_xor_sync(0xffffffffu, mx, o));
    }
    int lane = threadIdx.x & 31, wid = threadIdx.x >> 5;
    if (lane == 0) { sh[wid] = mn; sh[4 + wid] = mx; }
    __syncthreads();
    if (threadIdx.x == 0) {
        float a = sh[0], b2 = sh[4];
        #pragma unroll
        for (int k = 1; k < 4; k++) { a = fminf(a, sh[k]); b2 = fmaxf(b2, sh[4 + k]); }
        atomicMinF(&g_red[17], a);
        atomicMaxF(&g_red[22], b2);
    }
}

// ---------------- apply scale_diff + coef mix -> g_o65 ----------------
__global__ void k_apply65(const float* __restrict__ coef) {
    int i4 = blockIdx.x * 256 + threadIdx.x;
    int i  = i4 << 2;
    int bc = i >> 11;
    int c = bc % 65, b = bc / 65;
    int hw = i & 2047;
    int F = c / 13, v = c % 13;
    int fi = ((b * 13 + v) << 11) + hw;
    const float* dsrc = F == 0 ? g_dzd : F == 1 ? g_dq :
                        F == 2 ? g_accu : F == 3 ? g_accv : g_acct;
    float4 base = *reinterpret_cast<const float4*>(&g_fld[F][fi]);
    float4 diff = *reinterpret_cast<const float4*>(&dsrc[fi]);
    float mn = g_red[F], mx = g_red[5 + F];
    float me = g_red[10 + F] * (1.f / 212992.f);
    float a = (mn - me) * 0.05f;
    float bb = (mx - me) * 0.05f;
    float dmn = g_red[17 + F], dmx = g_red[22 + F];
    float sc = (bb - a) / (dmx - dmn);
    float4 cf = *reinterpret_cast<const float4*>(&coef[(c << 11) + hw]);
    float4 hv = *reinterpret_cast<const float4*>(&g_h[i]);
    float4 o;
    o.x = cf.x * (base.x + (diff.x - dmn) * sc + a) + (1.f - cf.x) * hv.x;
    o.y = cf.y * (base.y + (diff.y - dmn) * sc + a) + (1.f - cf.y) * hv.y;
    o.z = cf.z * (base.z + (diff.z - dmn) * sc + a) + (1.f - cf.z) * hv.z;
    o.w = cf.w * (base.w + (diff.w - dmn) * sc + a) + (1.f - cf.w) * hv.w;
    *reinterpret_cast<float4*>(&g_o65[i]) = o;
}

// ---------------- final: BN(o2) + x ----------------
__global__ void k_final(const float* __restrict__ x, const float* __restrict__ gblk,
                        const float* __restrict__ bblk, float* __restrict__ out) {
    int i4 = blockIdx.x * 256 + threadIdx.x;
    int i  = i4 << 2;
    int c = (i >> 11) & 255;
    float gsc = g_is256[c] * gblk[c];
    float m = g_m256[c], bia = bblk[c];
    float4 o2 = *reinterpret_cast<const float4*>(&g_o2[i]);
    float4 xv = *reinterpret_cast<const float4*>(&x[i]);
    float4 o;
    o.x = (o2.x - m) * gsc + bia + xv.x;
    o.y = (o2.y - m) * gsc + bia + xv.y;
    o.z = (o2.z - m) * gsc + bia + xv.z;
    o.w = (o2.w - m) * gsc + bia + xv.w;
    *reinterpret_cast<float4*>(&out[i]) = o;
}

// ---------------- launcher ----------------
extern "C" void kernel_launch(void* const* d_in, const int* in_sizes, int n_in,
                              void* d_out, int out_size) {
    const float* x        = (const float*)d_in[0];
    const float* w_norm   = (const float*)d_in[1];
    const float* b_norm   = (const float*)d_in[2];
    const float* w_innorm = (const float*)d_in[3];
    const float* b_innorm = (const float*)d_in[4];
    const float* coef     = (const float*)d_in[5];
    const float* gz = (const float*)d_in[6];  const float* bz = (const float*)d_in[7];
    const float* gq = (const float*)d_in[8];  const float* bq = (const float*)d_in[9];
    const float* gu = (const float*)d_in[10]; const float* bu = (const float*)d_in[11];
    const float* gv = (const float*)d_in[12]; const float* bv = (const float*)d_in[13];
    const float* gt = (const float*)d_in[14]; const float* bt = (const float*)d_in[15];
    const float* gblk = (const float*)d_in[16];
    const float* bblk = (const float*)d_in[17];
    float* out = (float*)d_out;

    k_init<<<1, 64>>>();
    k_conv<256, 65, 0><<<dim3(9, 4, 8), 64>>>(x, w_norm, b_norm);
    k_bnstats<65, 0><<<65, 256>>>();
    k_bnapply<<<NHE / 1024, 256>>>(gz, bz, gq, bq, gu, bu, gv, bv, gt, bt);
    k_basederiv<<<GF4, 256>>>();
    k_wvel<<<128, 128>>>();
    k_stage<<<GF4, 256>>>(0);
    for (int s = 1; s < 4; s++) {
        k_derivAll<<<GF4, 256>>>();
        k_stage<<<GF4, 256>>>(s);
    }
    k_zt<<<128, 128>>>();
    k_apply65<<<NHE / 1024, 256>>>(coef);
    k_conv<65, 256, 1><<<dim3(32, 4, 8), 64>>>(nullptr, w_innorm, b_innorm);
    k_bnstats<256, 1><<<256, 256>>>();
    k_final<<<NOE / 1024, 256>>>(x, gblk, bblk, out);
}